// round 3
// baseline (speedup 1.0000x reference)
#include <cuda_runtime.h>

#define Bsz 256
#define Csz 128
#define Nsz 64
#define Psz 16
#define Qsz 48
#define TB 128
#define SWEEPS 6

// ---------------- device scratch (no allocations allowed) ----------------
__device__ double gD[Csz * Nsz * Psz];      // per-channel sum of x_log
__device__ double gVarAcc[Csz];             // per-channel sum of theta^2 sums
__device__ double gBm[Csz * Qsz * Psz];     // per-channel Bm (48x16)
__device__ double gGinvC[Csz * Psz * Psz];  // per-channel (I + BmᵀBm/4)^-1
__device__ double gGinvB[Psz * Psz];        // bias (I + biasᵀbias/4)^-1
__device__ double gFactor[Csz];             // shift / sqrt(var + eps)

// ---------------- fp64 helpers: all assume blockDim.x == 128 ----------------

// Parallel-ordered cyclic Jacobi eig of symmetric 16x16 W (smem, fp64).
// On exit: diag(W) = eigenvalues, V = eigenvectors.
__device__ void jacobi16d(double* W, double* V, double* cs) {
    const int t = threadIdx.x;
    for (int i = t; i < 256; i += TB) V[i] = ((i >> 4) == (i & 15)) ? 1.0 : 0.0;
    __syncthreads();
    const int pr = t >> 4, el = t & 15;
    for (int sweep = 0; sweep < SWEEPS; ++sweep) {
        for (int r = 0; r < 15; ++r) {
            int p, q;
            if (pr == 0) { p = 15; q = r; }
            else { p = (r + pr) % 15; q = (r + 15 - pr) % 15; }
            if (p < q) { int tmp = p; p = q; q = tmp; }
            if (el == 0) {
                double app = W[p * 16 + p], aqq = W[q * 16 + q], apq = W[p * 16 + q];
                double c = 1.0, s = 0.0;
                if (fabs(apq) > 1e-300) {
                    double tau = (aqq - app) / (2.0 * apq);
                    double tt = copysign(1.0, tau) / (fabs(tau) + sqrt(1.0 + tau * tau));
                    c = rsqrt(1.0 + tt * tt);
                    s = tt * c;
                }
                cs[pr] = c; cs[8 + pr] = s;
            }
            __syncthreads();
            double c = cs[pr], s = cs[8 + pr];
            double wp = W[p * 16 + el], wq = W[q * 16 + el];
            W[p * 16 + el] = c * wp - s * wq;
            W[q * 16 + el] = s * wp + c * wq;
            __syncthreads();
            double xp = W[el * 16 + p], xq = W[el * 16 + q];
            W[el * 16 + p] = c * xp - s * xq;
            W[el * 16 + q] = s * xp + c * xq;
            double vp = V[el * 16 + p], vq = V[el * 16 + q];
            V[el * 16 + p] = c * vp - s * vq;
            V[el * 16 + q] = s * vp + c * vq;
            __syncthreads();
        }
    }
}

// Eigenvalues only (no V) — used by k3.
__device__ void jacobi16d_noV(double* W, double* cs) {
    const int t = threadIdx.x;
    const int pr = t >> 4, el = t & 15;
    for (int sweep = 0; sweep < SWEEPS; ++sweep) {
        for (int r = 0; r < 15; ++r) {
            int p, q;
            if (pr == 0) { p = 15; q = r; }
            else { p = (r + pr) % 15; q = (r + 15 - pr) % 15; }
            if (p < q) { int tmp = p; p = q; q = tmp; }
            if (el == 0) {
                double app = W[p * 16 + p], aqq = W[q * 16 + q], apq = W[p * 16 + q];
                double c = 1.0, s = 0.0;
                if (fabs(apq) > 1e-300) {
                    double tau = (aqq - app) / (2.0 * apq);
                    double tt = copysign(1.0, tau) / (fabs(tau) + sqrt(1.0 + tau * tau));
                    c = rsqrt(1.0 + tt * tt);
                    s = tt * c;
                }
                cs[pr] = c; cs[8 + pr] = s;
            }
            __syncthreads();
            double c = cs[pr], s = cs[8 + pr];
            double wp = W[p * 16 + el], wq = W[q * 16 + el];
            W[p * 16 + el] = c * wp - s * wq;
            W[q * 16 + el] = s * wp + c * wq;
            __syncthreads();
            double xp = W[el * 16 + p], xq = W[el * 16 + q];
            W[el * 16 + p] = c * xp - s * xq;
            W[el * 16 + q] = s * xp + c * xq;
            __syncthreads();
        }
    }
}

// Gauss-Jordan inverse with partial pivoting of 16x16 (fp64). aug: 16x32 smem.
__device__ void invert16d(const double* Min, double* aug, double* Mout, double* fs, int* piv) {
    const int t = threadIdx.x;
    for (int i = t; i < 512; i += TB) {
        int r = i >> 5, cc = i & 31;
        aug[i] = (cc < 16) ? Min[r * 16 + cc] : ((cc - 16 == r) ? 1.0 : 0.0);
    }
    __syncthreads();
    for (int k = 0; k < 16; ++k) {
        if (t == 0) {
            int best = k; double bv = fabs(aug[k * 32 + k]);
            for (int i = k + 1; i < 16; ++i) {
                double v = fabs(aug[i * 32 + k]);
                if (v > bv) { bv = v; best = i; }
            }
            *piv = best;
        }
        __syncthreads();
        int pb = *piv;
        if (pb != k && t < 32) {
            double tmp = aug[k * 32 + t];
            aug[k * 32 + t] = aug[pb * 32 + t];
            aug[pb * 32 + t] = tmp;
        }
        __syncthreads();
        if (t == 0) fs[16] = 1.0 / aug[k * 32 + k];
        __syncthreads();
        if (t < 32) aug[k * 32 + t] *= fs[16];
        __syncthreads();
        if (t < 16) fs[t] = aug[t * 32 + k];
        __syncthreads();
        for (int i = t; i < 512; i += TB) {
            int r = i >> 5, cc = i & 31;
            if (r != k) aug[i] -= fs[r] * aug[k * 32 + cc];
        }
        __syncthreads();
    }
    for (int i = t; i < 256; i += TB) Mout[i] = aug[(i >> 4) * 32 + 16 + (i & 15)];
    __syncthreads();
}

// C[m x 16] = A[m x 16] * B[16 x 16]
__device__ void matmul16d(const double* A, const double* Bm, double* Cc, int m) {
    const int t = threadIdx.x;
    for (int i = t; i < m * 16; i += TB) {
        int r = i >> 4, cc = i & 15;
        double acc = 0.0;
        #pragma unroll
        for (int x = 0; x < 16; ++x) acc += A[r * 16 + x] * Bm[x * 16 + cc];
        Cc[i] = acc;
    }
    __syncthreads();
}

// C[16x16] = Aᵀ B, A,B are m x 16
__device__ void atb16d(const double* A, const double* Bm, double* Cc, int m) {
    const int t = threadIdx.x;
    for (int i = t; i < 256; i += TB) {
        int r = i >> 4, cc = i & 15;
        double acc = 0.0;
        for (int x = 0; x < m; ++x) acc += A[x * 16 + r] * Bm[x * 16 + cc];
        Cc[i] = acc;
    }
    __syncthreads();
}

// W[16x16] = Aᵀ A, A is m x 16
__device__ void gram16d(const double* A, double* W, int m) {
    const int t = threadIdx.x;
    for (int i = t; i < 256; i += TB) {
        int r = i >> 4, cc = i & 15;
        double acc = 0.0;
        for (int x = 0; x < m; ++x) acc += A[x * 16 + r] * A[x * 16 + cc];
        W[i] = acc;
    }
    __syncthreads();
}

// P = V diag(g) Vᵀ
__device__ void vdvtd(const double* V, const double* g, double* P) {
    const int t = threadIdx.x;
    for (int i = t; i < 256; i += TB) {
        int r = i >> 4, cc = i & 15;
        double acc = 0.0;
        #pragma unroll
        for (int x = 0; x < 16; ++x) acc += V[r * 16 + x] * g[x] * V[cc * 16 + x];
        P[i] = acc;
    }
    __syncthreads();
}

// ---------------- kernels ----------------

__global__ void k0_zero() {
    int i = blockIdx.x * blockDim.x + threadIdx.x;
    if (i < Csz * Nsz * Psz) gD[i] = 0.0;
    if (i < Csz) gVarAcc[i] = 0.0;
}

// K1: per (b,c): x_log = log_map(X[0,c], X[b,c]); accumulate into gD[c]
__global__ void k1_logmap(const float* __restrict__ X) {
    __shared__ double U[1024], Xb[1024];
    __shared__ double M[256], W[256], V[256], aug[512];
    __shared__ double g[16], cs[16], fs[18];
    __shared__ int piv;
    const int bc = blockIdx.x;
    const int c = bc & (Csz - 1);
    const int t = threadIdx.x;
    const float* Xp = X + (size_t)bc * 1024;
    const float* Up = X + (size_t)c * 1024;   // b = 0
    for (int i = t; i < 1024; i += TB) { U[i] = (double)Up[i]; Xb[i] = (double)Xp[i]; }
    __syncthreads();
    atb16d(U, Xb, M, 64);                      // M = Uᵀ X (16x16)
    // Z = X - U M (in place in Xb)
    for (int i = t; i < 1024; i += TB) {
        int r = i >> 4, cc = i & 15;
        double acc = Xb[i];
        #pragma unroll
        for (int x = 0; x < 16; ++x) acc -= U[r * 16 + x] * M[x * 16 + cc];
        Xb[i] = acc;
    }
    __syncthreads();
    invert16d(M, aug, M, fs, &piv);            // M = inv(UᵀX)
    matmul16d(Xb, M, U, 64);                   // A = Z M^-1 (into U, dead)
    gram16d(U, W, 64);                         // W = AᵀA
    jacobi16d(W, V, cs);
    if (t < 16) {
        double S = sqrt(fmax(W[t * 17], 0.0));
        g[t] = (S > 1e-100) ? atan(S) / S : 1.0;
    }
    __syncthreads();
    vdvtd(V, g, M);                            // M = V diag(atan(S)/S) Vᵀ
    double* dst = gD + c * 1024;
    for (int i = t; i < 1024; i += TB) {
        int r = i >> 4, cc = i & 15;
        double acc = 0.0;
        #pragma unroll
        for (int x = 0; x < 16; ++x) acc += U[r * 16 + x] * M[x * 16 + cc];
        atomicAdd(&dst[i], acc);               // x_log accumulated over b
    }
}

// K2: per c: exp_map mean; Bm = log_identity_B(mean); GinvC
__global__ void k2_mean(const float* __restrict__ X, float* __restrict__ meanOut) {
    __shared__ double Dm[1024], U0[1024], meanS[1024], Cm[768];
    __shared__ double W[256], V[256], M1[256], M2[256], aug[512];
    __shared__ double g[32], cs[16], fs[18];
    __shared__ int piv;
    const int c = blockIdx.x;
    const int t = threadIdx.x;
    for (int i = t; i < 1024; i += TB) {
        Dm[i] = gD[c * 1024 + i] * (1.0 / (double)Bsz);
        U0[i] = (double)X[(size_t)c * 1024 + i];   // b = 0
    }
    __syncthreads();
    gram16d(Dm, W, 64);
    jacobi16d(W, V, cs);
    if (t < 16) {
        double S = sqrt(fmax(W[t * 17], 0.0));
        g[t] = cos(S);
        g[16 + t] = (S > 1e-100) ? sin(S) / S : 1.0;
    }
    __syncthreads();
    vdvtd(V, g, M1);                           // V cos(S) Vᵀ
    vdvtd(V, g + 16, M2);                      // V sinc(S) Vᵀ
    // mean = U0*M1 + D*M2
    for (int i = t; i < 1024; i += TB) {
        int r = i >> 4, cc = i & 15;
        double acc = 0.0;
        #pragma unroll
        for (int x = 0; x < 16; ++x)
            acc += U0[r * 16 + x] * M1[x * 16 + cc] + Dm[r * 16 + x] * M2[x * 16 + cc];
        meanS[i] = acc;
        meanOut[c * 1024 + i] = (float)acc;
    }
    __syncthreads();
    // Bm = log_identity_B(mean)
    invert16d(meanS, aug, M1, fs, &piv);       // inv(mean[:16,:])
    matmul16d(meanS + 256, M1, Cm, 48);        // Cm = mean[16:,:] inv(...)
    gram16d(Cm, W, 48);
    jacobi16d(W, V, cs);
    if (t < 16) {
        double S = sqrt(fmax(W[t * 17], 0.0));
        g[t] = (S > 1e-100) ? atan(S) / S : 1.0;
    }
    __syncthreads();
    vdvtd(V, g, M2);
    matmul16d(Cm, M2, Dm, 48);                 // Bm (48x16) into Dm buffer
    for (int i = t; i < 768; i += TB) gBm[c * 768 + i] = Dm[i];
    __syncthreads();
    // GinvC = inv(I + 0.25 BmᵀBm)
    gram16d(Dm, W, 48);
    for (int i = t; i < 256; i += TB) {
        int r = i >> 4, cc = i & 15;
        W[i] = 0.25 * W[i] + ((r == cc) ? 1.0 : 0.0);
    }
    __syncthreads();
    invert16d(W, aug, M1, fs, &piv);
    for (int i = t; i < 256; i += TB) gGinvC[c * 256 + i] = M1[i];
}

// K3: per (b,c): sum of theta^2 (principal angles between mean and X)
__global__ void k3_theta(const float* __restrict__ X, const float* __restrict__ meanIn) {
    __shared__ double Mn[1024], Xb[1024];
    __shared__ double M[256], W[256], cs[16];
    const int bc = blockIdx.x;
    const int c = bc & (Csz - 1);
    const int t = threadIdx.x;
    const float* Xp = X + (size_t)bc * 1024;
    for (int i = t; i < 1024; i += TB) {
        Mn[i] = (double)meanIn[c * 1024 + i];
        Xb[i] = (double)Xp[i];
    }
    __syncthreads();
    atb16d(Mn, Xb, M, 64);                     // meanᵀX (16x16)
    gram16d(M, W, 16);                         // MᵀM
    jacobi16d_noV(W, cs);
    if (t == 0) {
        double sum = 0.0;
        for (int j = 0; j < 16; ++j) {
            double s = sqrt(fmax(W[j * 17], 0.0));
            s = fmin(s, 1.0);
            double th = acos(s);
            sum += th * th;
        }
        atomicAdd(&gVarAcc[c], sum);
    }
}

// K4: factor per channel + bias Cayley Ginv (single block)
__global__ void k4_factor(const float* __restrict__ bias, const float* __restrict__ shiftp) {
    __shared__ double Bb[768], W[256], M1[256], aug[512], fs[18];
    __shared__ int piv;
    const int t = threadIdx.x;
    if (t < Csz) {
        double var = gVarAcc[t] * (1.0 / (double)Bsz);
        gFactor[t] = (double)shiftp[0] / sqrt(var + 1e-5);
    }
    for (int i = t; i < 768; i += TB) Bb[i] = (double)bias[i];
    __syncthreads();
    gram16d(Bb, W, 48);
    for (int i = t; i < 256; i += TB) {
        int r = i >> 4, cc = i & 15;
        W[i] = 0.25 * W[i] + ((r == cc) ? 1.0 : 0.0);
    }
    __syncthreads();
    invert16d(W, aug, M1, fs, &piv);
    for (int i = t; i < 256; i += TB) gGinvB[i] = M1[i];
}

// K5: per (b,c): X_centered = Rinv X; gyro scaling; X_norm = Rb X_scaled
__global__ void k5_final(const float* __restrict__ X, const float* __restrict__ bias,
                         float* __restrict__ out) {
    __shared__ double Xs[1024], Bmat[768], Cm[768];
    __shared__ double Ginv[256], T[256], Y[256], W[256], V[256], M2[256], aug[512];
    __shared__ double g[32], cs[16], fs[18];
    __shared__ int piv;
    const int bc = blockIdx.x;
    const int c = bc & (Csz - 1);
    const int t = threadIdx.x;
    const float* Xp = X + (size_t)bc * 1024;
    for (int i = t; i < 1024; i += TB) Xs[i] = (double)Xp[i];
    for (int i = t; i < 768; i += TB) Bmat[i] = gBm[c * 768 + i];
    for (int i = t; i < 256; i += TB) Ginv[i] = gGinvC[c * 256 + i];
    __syncthreads();
    // --- Step A: Rinv = cayley(b2skew(-Bm)) applied via Schur trick ---
    // T = Xu + 0.5 Bmᵀ Xl
    for (int i = t; i < 256; i += TB) {
        int r = i >> 4, cc = i & 15;
        double acc = Xs[i];
        for (int k = 0; k < 48; ++k)
            acc += 0.5 * Bmat[k * 16 + r] * Xs[256 + k * 16 + cc];
        T[i] = acc;
    }
    __syncthreads();
    matmul16d(Ginv, T, Y, 16);                 // Y = G^-1 T
    for (int i = t; i < 1024; i += TB) {
        if (i < 256) Xs[i] = 2.0 * Y[i] - Xs[i];            // top = 2Y - Xu
        else {
            int r = (i - 256) >> 4, cc = i & 15;
            double acc = Xs[i];                             // bot = Xl - Bm Y
            #pragma unroll
            for (int x = 0; x < 16; ++x) acc -= Bmat[r * 16 + x] * Y[x * 16 + cc];
            Xs[i] = acc;
        }
    }
    __syncthreads();
    // --- Step B: gyro scalar product with t = factor[c] ---
    invert16d(Xs, aug, M2, fs, &piv);          // inv(Xu)
    matmul16d(Xs + 256, M2, Cm, 48);           // Cm = Xl inv(Xu)
    gram16d(Cm, W, 48);
    jacobi16d(W, V, cs);
    double fct = gFactor[c];
    if (t < 16) {
        double S = sqrt(fmax(W[t * 17], 0.0));
        double th = fct * atan(S);
        g[t] = cos(th);
        g[16 + t] = (S > 1e-100) ? sin(th) / S : fct;
    }
    __syncthreads();
    vdvtd(V, g, T);                            // V cos(th) Vᵀ
    vdvtd(V, g + 16, Y);                       // V (sin(th)/S) Vᵀ
    for (int i = t; i < 1024; i += TB) {
        if (i < 256) Xs[i] = T[i];                          // top = V cos Vᵀ
        else {
            int r = (i - 256) >> 4, cc = i & 15;
            double acc = 0.0;                               // bot = Cm V sinfac Vᵀ
            #pragma unroll
            for (int x = 0; x < 16; ++x) acc += Cm[r * 16 + x] * Y[x * 16 + cc];
            Xs[i] = acc;
        }
    }
    __syncthreads();
    // --- Step C: Rb = cayley(b2skew(bias)) applied ---
    for (int i = t; i < 768; i += TB) Bmat[i] = (double)bias[i];
    for (int i = t; i < 256; i += TB) Ginv[i] = gGinvB[i];
    __syncthreads();
    for (int i = t; i < 256; i += TB) {
        int r = i >> 4, cc = i & 15;
        double acc = Xs[i];                    // T = Xu - 0.5 biasᵀ Xl
        for (int k = 0; k < 48; ++k)
            acc -= 0.5 * Bmat[k * 16 + r] * Xs[256 + k * 16 + cc];
        T[i] = acc;
    }
    __syncthreads();
    matmul16d(Ginv, T, Y, 16);
    float* dst = out + (size_t)bc * 1024;
    for (int i = t; i < 1024; i += TB) {
        if (i < 256) dst[i] = (float)(2.0 * Y[i] - Xs[i]);
        else {
            int r = (i - 256) >> 4, cc = i & 15;
            double acc = Xs[i];
            #pragma unroll
            for (int x = 0; x < 16; ++x) acc += Bmat[r * 16 + x] * Y[x * 16 + cc];
            dst[i] = (float)acc;
        }
    }
}

// ---------------- launch ----------------
extern "C" void kernel_launch(void* const* d_in, const int* in_sizes, int n_in,
                              void* d_out, int out_size) {
    const float* X = (const float*)d_in[0];
    const float* bias = (const float*)d_in[1];
    const float* shift = (const float*)d_in[2];
    float* out = (float*)d_out;
    float* meanOut = out + (size_t)Bsz * Csz * Nsz * Psz;  // mean appended after X_normalized

    k0_zero<<<(Csz * Nsz * Psz + 255) / 256, 256>>>();
    k1_logmap<<<Bsz * Csz, TB>>>(X);
    k2_mean<<<Csz, TB>>>(X, meanOut);
    k3_theta<<<Bsz * Csz, TB>>>(X, meanOut);
    k4_factor<<<1, TB>>>(bias, shift);
    k5_final<<<Bsz * Csz, TB>>>(X, bias, out);
}

// round 4
// speedup vs baseline: 11.6916x; 11.6916x over previous
#include <cuda_runtime.h>

#define Bsz 256
#define Csz 128
#define Nsz 64
#define Psz 16
#define Qsz 48
#define TB 128
#define SWEEPS 6
#define SWEEPS_NV 5

// ---------------- device scratch ----------------
__device__ float  gD[Csz * Nsz * Psz];       // per-channel sum of x_log (fp32 atomics)
__device__ float  gVarAcc[Csz];              // per-channel sum of theta^2
__device__ float  gBmF[Csz * Qsz * Psz];     // per-channel Bm (48x16) fp32
__device__ float  gGinvCF[Csz * Psz * Psz];  // per-channel (I + BmᵀBm/4)^-1 fp32
__device__ float  gGinvBF[Psz * Psz];        // bias (I + biasᵀbias/4)^-1 fp32
__device__ float  gFactorF[Csz];             // shift / sqrt(var + eps) fp32

// ================= fp32 helpers (blockDim.x == 128) =================

// Parallel-ordered cyclic Jacobi eig of symmetric 16x16 W. V out = eigvecs.
__device__ void jacobi16(float* W, float* V, float* cs) {
    const int t = threadIdx.x;
    for (int i = t; i < 256; i += TB) V[i] = ((i >> 4) == (i & 15)) ? 1.f : 0.f;
    __syncthreads();
    const int pr = t >> 4, el = t & 15;
    for (int sweep = 0; sweep < SWEEPS; ++sweep) {
        for (int r = 0; r < 15; ++r) {
            int p, q;
            if (pr == 0) { p = 15; q = r; }
            else { p = (r + pr) % 15; q = (r + 15 - pr) % 15; }
            if (p < q) { int tmp = p; p = q; q = tmp; }
            if (el == 0) {
                float app = W[p * 16 + p], aqq = W[q * 16 + q], apq = W[p * 16 + q];
                float c = 1.f, s = 0.f;
                if (fabsf(apq) > 1e-37f) {
                    float tau = (aqq - app) / (2.f * apq);
                    float tt = copysignf(1.f, tau) / (fabsf(tau) + sqrtf(1.f + tau * tau));
                    c = rsqrtf(1.f + tt * tt);
                    s = tt * c;
                }
                cs[pr] = c; cs[8 + pr] = s;
            }
            __syncthreads();
            float c = cs[pr], s = cs[8 + pr];
            float wp = W[p * 16 + el], wq = W[q * 16 + el];
            W[p * 16 + el] = c * wp - s * wq;
            W[q * 16 + el] = s * wp + c * wq;
            __syncthreads();
            float xp = W[el * 16 + p], xq = W[el * 16 + q];
            W[el * 16 + p] = c * xp - s * xq;
            W[el * 16 + q] = s * xp + c * xq;
            float vp = V[el * 16 + p], vq = V[el * 16 + q];
            V[el * 16 + p] = c * vp - s * vq;
            V[el * 16 + q] = s * vp + c * vq;
            __syncthreads();
        }
    }
}

// Eigenvalues only.
__device__ void jacobi16nv(float* W, float* cs) {
    const int t = threadIdx.x;
    const int pr = t >> 4, el = t & 15;
    for (int sweep = 0; sweep < SWEEPS_NV; ++sweep) {
        for (int r = 0; r < 15; ++r) {
            int p, q;
            if (pr == 0) { p = 15; q = r; }
            else { p = (r + pr) % 15; q = (r + 15 - pr) % 15; }
            if (p < q) { int tmp = p; p = q; q = tmp; }
            if (el == 0) {
                float app = W[p * 16 + p], aqq = W[q * 16 + q], apq = W[p * 16 + q];
                float c = 1.f, s = 0.f;
                if (fabsf(apq) > 1e-37f) {
                    float tau = (aqq - app) / (2.f * apq);
                    float tt = copysignf(1.f, tau) / (fabsf(tau) + sqrtf(1.f + tau * tau));
                    c = rsqrtf(1.f + tt * tt);
                    s = tt * c;
                }
                cs[pr] = c; cs[8 + pr] = s;
            }
            __syncthreads();
            float c = cs[pr], s = cs[8 + pr];
            float wp = W[p * 16 + el], wq = W[q * 16 + el];
            W[p * 16 + el] = c * wp - s * wq;
            W[q * 16 + el] = s * wp + c * wq;
            __syncthreads();
            float xp = W[el * 16 + p], xq = W[el * 16 + q];
            W[el * 16 + p] = c * xp - s * xq;
            W[el * 16 + q] = s * xp + c * xq;
            __syncthreads();
        }
    }
}

// C[m x 16] = A[m x 16] * B[16 x 16]
__device__ void matmul16(const float* A, const float* Bm, float* Cc, int m) {
    const int t = threadIdx.x;
    for (int i = t; i < m * 16; i += TB) {
        int r = i >> 4, cc = i & 15;
        float acc = 0.f;
        #pragma unroll
        for (int x = 0; x < 16; ++x) acc += A[r * 16 + x] * Bm[x * 16 + cc];
        Cc[i] = acc;
    }
    __syncthreads();
}

// C[16x16] = Aᵀ B, A,B are m x 16
__device__ void atb16(const float* A, const float* Bm, float* Cc, int m) {
    const int t = threadIdx.x;
    for (int i = t; i < 256; i += TB) {
        int r = i >> 4, cc = i & 15;
        float acc = 0.f;
        for (int x = 0; x < m; ++x) acc += A[x * 16 + r] * Bm[x * 16 + cc];
        Cc[i] = acc;
    }
    __syncthreads();
}

// W = A Aᵀ for A 16x16 (row gram, bounded for orthonormal-derived A)
__device__ void gramT16(const float* A, float* W) {
    const int t = threadIdx.x;
    for (int i = t; i < 256; i += TB) {
        int r = i >> 4, cc = i & 15;
        float acc = 0.f;
        #pragma unroll
        for (int x = 0; x < 16; ++x) acc += A[r * 16 + x] * A[cc * 16 + x];
        W[i] = acc;
    }
    __syncthreads();
}

// W = Aᵀ A for A m x 16
__device__ void gram16(const float* A, float* W, int m) {
    const int t = threadIdx.x;
    for (int i = t; i < 256; i += TB) {
        int r = i >> 4, cc = i & 15;
        float acc = 0.f;
        for (int x = 0; x < m; ++x) acc += A[x * 16 + r] * A[x * 16 + cc];
        W[i] = acc;
    }
    __syncthreads();
}

// P = V diag(g) Vᵀ (fp32)
__device__ void vdvt(const float* V, const float* g, float* P) {
    const int t = threadIdx.x;
    for (int i = t; i < 256; i += TB) {
        int r = i >> 4, cc = i & 15;
        float acc = 0.f;
        #pragma unroll
        for (int x = 0; x < 16; ++x) acc += V[r * 16 + x] * g[x] * V[cc * 16 + x];
        P[i] = acc;
    }
    __syncthreads();
}

// ================= fp64 helpers (k2/k4 only) =================

__device__ void jacobi16d(double* W, double* V, double* cs) {
    const int t = threadIdx.x;
    for (int i = t; i < 256; i += TB) V[i] = ((i >> 4) == (i & 15)) ? 1.0 : 0.0;
    __syncthreads();
    const int pr = t >> 4, el = t & 15;
    for (int sweep = 0; sweep < SWEEPS; ++sweep) {
        for (int r = 0; r < 15; ++r) {
            int p, q;
            if (pr == 0) { p = 15; q = r; }
            else { p = (r + pr) % 15; q = (r + 15 - pr) % 15; }
            if (p < q) { int tmp = p; p = q; q = tmp; }
            if (el == 0) {
                double app = W[p * 16 + p], aqq = W[q * 16 + q], apq = W[p * 16 + q];
                double c = 1.0, s = 0.0;
                if (fabs(apq) > 1e-300) {
                    double tau = (aqq - app) / (2.0 * apq);
                    double tt = copysign(1.0, tau) / (fabs(tau) + sqrt(1.0 + tau * tau));
                    c = rsqrt(1.0 + tt * tt);
                    s = tt * c;
                }
                cs[pr] = c; cs[8 + pr] = s;
            }
            __syncthreads();
            double c = cs[pr], s = cs[8 + pr];
            double wp = W[p * 16 + el], wq = W[q * 16 + el];
            W[p * 16 + el] = c * wp - s * wq;
            W[q * 16 + el] = s * wp + c * wq;
            __syncthreads();
            double xp = W[el * 16 + p], xq = W[el * 16 + q];
            W[el * 16 + p] = c * xp - s * xq;
            W[el * 16 + q] = s * xp + c * xq;
            double vp = V[el * 16 + p], vq = V[el * 16 + q];
            V[el * 16 + p] = c * vp - s * vq;
            V[el * 16 + q] = s * vp + c * vq;
            __syncthreads();
        }
    }
}

__device__ void invert16d(const double* Min, double* aug, double* Mout, double* fs, int* piv) {
    const int t = threadIdx.x;
    for (int i = t; i < 512; i += TB) {
        int r = i >> 5, cc = i & 31;
        aug[i] = (cc < 16) ? Min[r * 16 + cc] : ((cc - 16 == r) ? 1.0 : 0.0);
    }
    __syncthreads();
    for (int k = 0; k < 16; ++k) {
        if (t == 0) {
            int best = k; double bv = fabs(aug[k * 32 + k]);
            for (int i = k + 1; i < 16; ++i) {
                double v = fabs(aug[i * 32 + k]);
                if (v > bv) { bv = v; best = i; }
            }
            *piv = best;
        }
        __syncthreads();
        int pb = *piv;
        if (pb != k && t < 32) {
            double tmp = aug[k * 32 + t];
            aug[k * 32 + t] = aug[pb * 32 + t];
            aug[pb * 32 + t] = tmp;
        }
        __syncthreads();
        if (t == 0) fs[16] = 1.0 / aug[k * 32 + k];
        __syncthreads();
        if (t < 32) aug[k * 32 + t] *= fs[16];
        __syncthreads();
        if (t < 16) fs[t] = aug[t * 32 + k];
        __syncthreads();
        for (int i = t; i < 512; i += TB) {
            int r = i >> 5, cc = i & 31;
            if (r != k) aug[i] -= fs[r] * aug[k * 32 + cc];
        }
        __syncthreads();
    }
    for (int i = t; i < 256; i += TB) Mout[i] = aug[(i >> 4) * 32 + 16 + (i & 15)];
    __syncthreads();
}

__device__ void matmul16d(const double* A, const double* Bm, double* Cc, int m) {
    const int t = threadIdx.x;
    for (int i = t; i < m * 16; i += TB) {
        int r = i >> 4, cc = i & 15;
        double acc = 0.0;
        #pragma unroll
        for (int x = 0; x < 16; ++x) acc += A[r * 16 + x] * Bm[x * 16 + cc];
        Cc[i] = acc;
    }
    __syncthreads();
}

__device__ void gram16d(const double* A, double* W, int m) {
    const int t = threadIdx.x;
    for (int i = t; i < 256; i += TB) {
        int r = i >> 4, cc = i & 15;
        double acc = 0.0;
        for (int x = 0; x < m; ++x) acc += A[x * 16 + r] * A[x * 16 + cc];
        W[i] = acc;
    }
    __syncthreads();
}

__device__ void vdvtd(const double* V, const double* g, double* P) {
    const int t = threadIdx.x;
    for (int i = t; i < 256; i += TB) {
        int r = i >> 4, cc = i & 15;
        double acc = 0.0;
        #pragma unroll
        for (int x = 0; x < 16; ++x) acc += V[r * 16 + x] * g[x] * V[cc * 16 + x];
        P[i] = acc;
    }
    __syncthreads();
}

// ================= kernels =================

__global__ void k0_zero() {
    int i = blockIdx.x * blockDim.x + threadIdx.x;
    if (i < Csz * Nsz * Psz) gD[i] = 0.f;
    if (i < Csz) gVarAcc[i] = 0.f;
}

// K1: x_log = log_map(X[0,c], X[b,c]) accumulated into gD[c].
// Stable form: K = M Mᵀ (M = UᵀX, bounded), eig(K)=W,λ;
// G = MᵀW diag(atan(S)/(S λ)) Wᵀ  (== M⁻¹ W f Wᵀ);  x_log = (X − U M) G.
__global__ void k1_logmap(const float* __restrict__ X) {
    __shared__ float U[1024], Xb[1024];
    __shared__ float M[256], W[256], V[256], cs[16];
    __shared__ double Md[256], Wd[256], T1d[256], fld[16];
    const int bc = blockIdx.x;
    const int c = bc & (Csz - 1);
    const int t = threadIdx.x;
    const float* Xp = X + (size_t)bc * 1024;
    const float* Up = X + (size_t)c * 1024;   // b = 0
    for (int i = t; i < 1024; i += TB) { U[i] = Up[i]; Xb[i] = Xp[i]; }
    __syncthreads();
    atb16(U, Xb, M, 64);                       // M = UᵀX
    for (int i = t; i < 1024; i += TB) {       // Z = X - U M (in place)
        int r = i >> 4, cc = i & 15;
        float acc = Xb[i];
        #pragma unroll
        for (int x = 0; x < 16; ++x) acc -= U[r * 16 + x] * M[x * 16 + cc];
        Xb[i] = acc;
    }
    __syncthreads();
    gramT16(M, W);                             // K = M Mᵀ (bounded)
    jacobi16(W, V, cs);                        // V = eigvecs (fp32)
    for (int i = t; i < 256; i += TB) { Md[i] = (double)M[i]; Wd[i] = (double)V[i]; }
    __syncthreads();
    // T1 = Mᵀ W (fp64)
    for (int i = t; i < 256; i += TB) {
        int r = i >> 4, cc = i & 15;
        double acc = 0.0;
        #pragma unroll
        for (int x = 0; x < 16; ++x) acc += Md[x * 16 + r] * Wd[x * 16 + cc];
        T1d[i] = acc;
    }
    __syncthreads();
    if (t < 16) {
        double lh = 0.0, nr = 0.0;
        #pragma unroll
        for (int i = 0; i < 16; ++i) {
            double a = T1d[i * 16 + t]; lh += a * a;
            double w = Wd[i * 16 + t];  nr += w * w;
        }
        double lam = lh / nr;
        lam = fmax(lam, 1e-30);
        double om = fmax(1.0 - lam, 0.0);
        double fl;
        if (om < 1e-30) fl = 1.0 / lam;
        else {
            double S = sqrt(om / lam);
            fl = atan(S) / (S * lam);
        }
        fld[t] = fl;
    }
    __syncthreads();
    // G = T1 diag(fl) Wᵀ (fp64), cast to fp32 into M
    for (int i = t; i < 256; i += TB) {
        int r = i >> 4, cc = i & 15;
        double acc = 0.0;
        #pragma unroll
        for (int x = 0; x < 16; ++x) acc += T1d[r * 16 + x] * fld[x] * Wd[cc * 16 + x];
        M[i] = (float)acc;
    }
    __syncthreads();
    float* dst = gD + c * 1024;
    for (int i = t; i < 1024; i += TB) {       // x_log = Z G, accumulate
        int r = i >> 4, cc = i & 15;
        float acc = 0.f;
        #pragma unroll
        for (int x = 0; x < 16; ++x) acc += Xb[r * 16 + x] * M[x * 16 + cc];
        atomicAdd(&dst[i], acc);
    }
}

// K2: per c (fp64, 128 blocks): exp_map mean; Bm; GinvC
__global__ void k2_mean(const float* __restrict__ X, float* __restrict__ meanOut) {
    __shared__ double Dm[1024], U0[1024], meanS[1024], Cm[768];
    __shared__ double W[256], V[256], M1[256], M2[256], aug[512];
    __shared__ double g[32], cs[16], fs[18];
    __shared__ int piv;
    const int c = blockIdx.x;
    const int t = threadIdx.x;
    for (int i = t; i < 1024; i += TB) {
        Dm[i] = (double)gD[c * 1024 + i] * (1.0 / (double)Bsz);
        U0[i] = (double)X[(size_t)c * 1024 + i];
    }
    __syncthreads();
    gram16d(Dm, W, 64);
    jacobi16d(W, V, cs);
    if (t < 16) {
        double S = sqrt(fmax(W[t * 17], 0.0));
        g[t] = cos(S);
        g[16 + t] = (S > 1e-100) ? sin(S) / S : 1.0;
    }
    __syncthreads();
    vdvtd(V, g, M1);
    vdvtd(V, g + 16, M2);
    for (int i = t; i < 1024; i += TB) {
        int r = i >> 4, cc = i & 15;
        double acc = 0.0;
        #pragma unroll
        for (int x = 0; x < 16; ++x)
            acc += U0[r * 16 + x] * M1[x * 16 + cc] + Dm[r * 16 + x] * M2[x * 16 + cc];
        meanS[i] = acc;
        meanOut[c * 1024 + i] = (float)acc;
    }
    __syncthreads();
    invert16d(meanS, aug, M1, fs, &piv);       // inv(mean[:16,:])
    matmul16d(meanS + 256, M1, Cm, 48);        // Cm
    gram16d(Cm, W, 48);
    jacobi16d(W, V, cs);
    if (t < 16) {
        double S = sqrt(fmax(W[t * 17], 0.0));
        g[t] = (S > 1e-100) ? atan(S) / S : 1.0;
    }
    __syncthreads();
    vdvtd(V, g, M2);
    matmul16d(Cm, M2, Dm, 48);                 // Bm (48x16)
    for (int i = t; i < 768; i += TB) gBmF[c * 768 + i] = (float)Dm[i];
    __syncthreads();
    gram16d(Dm, W, 48);
    for (int i = t; i < 256; i += TB) {
        int r = i >> 4, cc = i & 15;
        W[i] = 0.25 * W[i] + ((r == cc) ? 1.0 : 0.0);
    }
    __syncthreads();
    invert16d(W, aug, M1, fs, &piv);
    for (int i = t; i < 256; i += TB) gGinvCF[c * 256 + i] = (float)M1[i];
}

// K3: per (b,c): sum of theta^2 (fp32)
__global__ void k3_theta(const float* __restrict__ X, const float* __restrict__ meanIn) {
    __shared__ float Mn[1024], Xb[1024];
    __shared__ float M[256], W[256], cs[16];
    const int bc = blockIdx.x;
    const int c = bc & (Csz - 1);
    const int t = threadIdx.x;
    const float* Xp = X + (size_t)bc * 1024;
    for (int i = t; i < 1024; i += TB) { Mn[i] = meanIn[c * 1024 + i]; Xb[i] = Xp[i]; }
    __syncthreads();
    atb16(Mn, Xb, M, 64);                      // meanᵀX
    gram16(M, W, 16);                          // MᵀM (bounded)
    jacobi16nv(W, cs);
    if (t == 0) {
        float sum = 0.f;
        for (int j = 0; j < 16; ++j) {
            float s = sqrtf(fmaxf(W[j * 17], 0.f));
            s = fminf(s, 1.f);
            float th = acosf(s);
            sum += th * th;
        }
        atomicAdd(&gVarAcc[c], sum);
    }
}

// K4: factor per channel + bias Cayley Ginv (fp64, single block)
__global__ void k4_factor(const float* __restrict__ bias, const float* __restrict__ shiftp) {
    __shared__ double Bb[768], W[256], M1[256], aug[512], fs[18];
    __shared__ int piv;
    const int t = threadIdx.x;
    if (t < Csz) {
        double var = (double)gVarAcc[t] * (1.0 / (double)Bsz);
        gFactorF[t] = (float)((double)shiftp[0] / sqrt(var + 1e-5));
    }
    for (int i = t; i < 768; i += TB) Bb[i] = (double)bias[i];
    __syncthreads();
    gram16d(Bb, W, 48);
    for (int i = t; i < 256; i += TB) {
        int r = i >> 4, cc = i & 15;
        W[i] = 0.25 * W[i] + ((r == cc) ? 1.0 : 0.0);
    }
    __syncthreads();
    invert16d(W, aug, M1, fs, &piv);
    for (int i = t; i < 256; i += TB) gGinvBF[i] = (float)M1[i];
}

// K5: Cayley-center -> gyro-scale -> Cayley-bias, per (b,c).
__global__ void k5_final(const float* __restrict__ X, const float* __restrict__ bias,
                         float* __restrict__ out) {
    __shared__ float Xs[1024], Bmat[768];
    __shared__ float Ginv[256], T[256], Y[256], W[256], V[256];
    __shared__ float g[16], cs[16];
    __shared__ double Xud[256], Wd[256], T1d[256], hd[16];
    const int bc = blockIdx.x;
    const int c = bc & (Csz - 1);
    const int t = threadIdx.x;
    const float* Xp = X + (size_t)bc * 1024;
    for (int i = t; i < 1024; i += TB) Xs[i] = Xp[i];
    for (int i = t; i < 768; i += TB) Bmat[i] = gBmF[c * 768 + i];
    for (int i = t; i < 256; i += TB) Ginv[i] = gGinvCF[c * 256 + i];
    __syncthreads();
    // --- Step A: centering Cayley (Rinv = cayley(-skew(Bm))) ---
    for (int i = t; i < 256; i += TB) {
        int r = i >> 4, cc = i & 15;
        float acc = Xs[i];
        for (int k = 0; k < 48; ++k)
            acc += 0.5f * Bmat[k * 16 + r] * Xs[256 + k * 16 + cc];
        T[i] = acc;
    }
    __syncthreads();
    matmul16(Ginv, T, Y, 16);
    for (int i = t; i < 1024; i += TB) {
        if (i < 256) Xs[i] = 2.f * Y[i] - Xs[i];
        else {
            int r = (i - 256) >> 4, cc = i & 15;
            float acc = Xs[i];
            #pragma unroll
            for (int x = 0; x < 16; ++x) acc -= Bmat[r * 16 + x] * Y[x * 16 + cc];
            Xs[i] = acc;
        }
    }
    __syncthreads();
    // --- Step B: gyro scaling via K = Xu Xuᵀ (no inverse) ---
    gramT16(Xs, W);                            // K (bounded)
    jacobi16(W, V, cs);                        // eigvecs fp32
    for (int i = t; i < 256; i += TB) { Xud[i] = (double)Xs[i]; Wd[i] = (double)V[i]; }
    __syncthreads();
    for (int i = t; i < 256; i += TB) {        // T1 = Xuᵀ W (fp64)
        int r = i >> 4, cc = i & 15;
        double acc = 0.0;
        #pragma unroll
        for (int x = 0; x < 16; ++x) acc += Xud[x * 16 + r] * Wd[x * 16 + cc];
        T1d[i] = acc;
    }
    __syncthreads();
    float fct = gFactorF[c];
    if (t < 16) {
        double lh = 0.0, nr = 0.0;
        #pragma unroll
        for (int i = 0; i < 16; ++i) {
            double a = T1d[i * 16 + t]; lh += a * a;
            double w = Wd[i * 16 + t];  nr += w * w;
        }
        double lam = fmax(lh / nr, 1e-30);
        double om = fmax(1.0 - lam, 0.0);
        double th, h;
        if (om < 1e-30) { th = 0.0; h = (double)fct; }
        else {
            double S = sqrt(om / lam);
            th = (double)fct * atan(S);
            h = sin(th) / sqrt(lam * om);
        }
        g[t] = (float)cos(th);
        hd[t] = h;
    }
    __syncthreads();
    // M2 = T1 diag(h) Wᵀ (fp64 -> fp32 into Y)
    for (int i = t; i < 256; i += TB) {
        int r = i >> 4, cc = i & 15;
        double acc = 0.0;
        #pragma unroll
        for (int x = 0; x < 16; ++x) acc += T1d[r * 16 + x] * hd[x] * Wd[cc * 16 + x];
        Y[i] = (float)acc;
    }
    __syncthreads();
    vdvt(V, g, T);                             // top = W cos(th) Wᵀ
    // stash Xl into Bmat (no longer needed), then overwrite Xs
    for (int i = t; i < 768; i += TB) Bmat[i] = Xs[256 + i];
    __syncthreads();
    for (int i = t; i < 1024; i += TB) {
        if (i < 256) Xs[i] = T[i];
        else {
            int r = (i - 256) >> 4, cc = i & 15;
            float acc = 0.f;                   // bot = Xl M2
            #pragma unroll
            for (int x = 0; x < 16; ++x) acc += Bmat[r * 16 + x] * Y[x * 16 + cc];
            Xs[i] = acc;
        }
    }
    __syncthreads();
    // --- Step C: bias Cayley (Rb = cayley(+skew(bias))) ---
    for (int i = t; i < 768; i += TB) Bmat[i] = bias[i];
    for (int i = t; i < 256; i += TB) Ginv[i] = gGinvBF[i];
    __syncthreads();
    for (int i = t; i < 256; i += TB) {
        int r = i >> 4, cc = i & 15;
        float acc = Xs[i];
        for (int k = 0; k < 48; ++k)
            acc -= 0.5f * Bmat[k * 16 + r] * Xs[256 + k * 16 + cc];
        T[i] = acc;
    }
    __syncthreads();
    matmul16(Ginv, T, Y, 16);
    float* dst = out + (size_t)bc * 1024;
    for (int i = t; i < 1024; i += TB) {
        if (i < 256) dst[i] = 2.f * Y[i] - Xs[i];
        else {
            int r = (i - 256) >> 4, cc = i & 15;
            float acc = Xs[i];
            #pragma unroll
            for (int x = 0; x < 16; ++x) acc += Bmat[r * 16 + x] * Y[x * 16 + cc];
            dst[i] = acc;
        }
    }
}

// ---------------- launch ----------------
extern "C" void kernel_launch(void* const* d_in, const int* in_sizes, int n_in,
                              void* d_out, int out_size) {
    const float* X = (const float*)d_in[0];
    const float* bias = (const float*)d_in[1];
    const float* shift = (const float*)d_in[2];
    float* out = (float*)d_out;
    float* meanOut = out + (size_t)Bsz * Csz * Nsz * Psz;

    k0_zero<<<(Csz * Nsz * Psz + 255) / 256, 256>>>();
    k1_logmap<<<Bsz * Csz, TB>>>(X);
    k2_mean<<<Csz, TB>>>(X, meanOut);
    k3_theta<<<Bsz * Csz, TB>>>(X, meanOut);
    k4_factor<<<1, TB>>>(bias, shift);
    k5_final<<<Bsz * Csz, TB>>>(X, bias, out);
}

// round 5
// speedup vs baseline: 18.6076x; 1.5915x over previous
#include <cuda_runtime.h>

#define Bsz 256
#define Csz 128
#define Nsz 64
#define Psz 16
#define Qsz 48
#define TB 128
#define WPB 4
#define SWEEPS 6
#define SWEEPS_NV 5
#define S17 17

// ---------------- device scratch (static, no allocations) ----------------
__device__ float gXlog[(size_t)Bsz * Csz * Nsz * Psz]; // per-(b,c) x_log (128MB)
__device__ float gTheta[Bsz * Csz];                    // per-(b,c) theta^2 sum
__device__ float gBmF[Csz * Qsz * Psz];                // per-channel Bm (48x16)
__device__ float gGinvCF[Csz * Psz * Psz];             // (I + Bm'Bm/4)^-1
__device__ float gGinvBF[Psz * Psz];                   // bias (I + b'b/4)^-1
__device__ float gFactorF[Csz];                        // shift / sqrt(var+eps)

// ================= warp-level helpers (32 lanes per instance) =================

// Parallel-ordered cyclic Jacobi on symmetric 16x16 W (stride 17 smem).
// wantV: also accumulate eigenvectors into V (stride 17, caller-initialized I).
__device__ __forceinline__ void jacobi_warp(float* W, float* V, int lane,
                                            int sweeps, bool wantV) {
    const int j = lane >> 2;          // pair id 0..7
    const int b4 = (lane & 3) * 4;    // col/row base
    for (int sweep = 0; sweep < sweeps; ++sweep) {
        for (int r = 0; r < 15; ++r) {
            int p, q;
            if (j == 0) { p = 15; q = r; }
            else { p = (r + j) % 15; q = (r + 15 - j) % 15; }
            if (p < q) { int tmp = p; p = q; q = tmp; }
            __syncwarp();
            float c = 1.f, s = 0.f;
            if ((lane & 3) == 0) {
                float app = W[p * S17 + p], aqq = W[q * S17 + q], apq = W[p * S17 + q];
                if (fabsf(apq) > 1e-37f) {
                    float tau = (aqq - app) / (2.f * apq);
                    float tt = copysignf(1.f, tau) / (fabsf(tau) + sqrtf(1.f + tau * tau));
                    c = rsqrtf(1.f + tt * tt);
                    s = tt * c;
                }
            }
            c = __shfl_sync(0xffffffffu, c, lane & ~3);
            s = __shfl_sync(0xffffffffu, s, lane & ~3);
            // row phase: rows p,q / cols b4..b4+3 (disjoint rows across pairs)
            #pragma unroll
            for (int k = 0; k < 4; ++k) {
                int col = b4 + k;
                float wp = W[p * S17 + col], wq = W[q * S17 + col];
                W[p * S17 + col] = c * wp - s * wq;
                W[q * S17 + col] = s * wp + c * wq;
            }
            __syncwarp();
            // col phase: rows b4..b4+3 / cols p,q (disjoint cols across pairs)
            #pragma unroll
            for (int k = 0; k < 4; ++k) {
                int row = b4 + k;
                float xp = W[row * S17 + p], xq = W[row * S17 + q];
                W[row * S17 + p] = c * xp - s * xq;
                W[row * S17 + q] = s * xp + c * xq;
                if (wantV) {
                    float vp = V[row * S17 + p], vq = V[row * S17 + q];
                    V[row * S17 + p] = c * vp - s * vq;
                    V[row * S17 + q] = s * vp + c * vq;
                }
            }
        }
    }
    __syncwarp();
}

// ================= block-level fp64 helpers (k2/k4 only, blockDim=128) =================

__device__ void jacobi16d(double* W, double* V, double* cs) {
    const int t = threadIdx.x;
    for (int i = t; i < 256; i += TB) V[i] = ((i >> 4) == (i & 15)) ? 1.0 : 0.0;
    __syncthreads();
    const int pr = t >> 4, el = t & 15;
    for (int sweep = 0; sweep < SWEEPS; ++sweep) {
        for (int r = 0; r < 15; ++r) {
            int p, q;
            if (pr == 0) { p = 15; q = r; }
            else { p = (r + pr) % 15; q = (r + 15 - pr) % 15; }
            if (p < q) { int tmp = p; p = q; q = tmp; }
            if (el == 0) {
                double app = W[p * 16 + p], aqq = W[q * 16 + q], apq = W[p * 16 + q];
                double c = 1.0, s = 0.0;
                if (fabs(apq) > 1e-300) {
                    double tau = (aqq - app) / (2.0 * apq);
                    double tt = copysign(1.0, tau) / (fabs(tau) + sqrt(1.0 + tau * tau));
                    c = rsqrt(1.0 + tt * tt);
                    s = tt * c;
                }
                cs[pr] = c; cs[8 + pr] = s;
            }
            __syncthreads();
            double c = cs[pr], s = cs[8 + pr];
            double wp = W[p * 16 + el], wq = W[q * 16 + el];
            W[p * 16 + el] = c * wp - s * wq;
            W[q * 16 + el] = s * wp + c * wq;
            __syncthreads();
            double xp = W[el * 16 + p], xq = W[el * 16 + q];
            W[el * 16 + p] = c * xp - s * xq;
            W[el * 16 + q] = s * xp + c * xq;
            double vp = V[el * 16 + p], vq = V[el * 16 + q];
            V[el * 16 + p] = c * vp - s * vq;
            V[el * 16 + q] = s * vp + c * vq;
            __syncthreads();
        }
    }
}

__device__ void invert16d(const double* Min, double* aug, double* Mout, double* fs, int* piv) {
    const int t = threadIdx.x;
    for (int i = t; i < 512; i += TB) {
        int r = i >> 5, cc = i & 31;
        aug[i] = (cc < 16) ? Min[r * 16 + cc] : ((cc - 16 == r) ? 1.0 : 0.0);
    }
    __syncthreads();
    for (int k = 0; k < 16; ++k) {
        if (t == 0) {
            int best = k; double bv = fabs(aug[k * 32 + k]);
            for (int i = k + 1; i < 16; ++i) {
                double v = fabs(aug[i * 32 + k]);
                if (v > bv) { bv = v; best = i; }
            }
            *piv = best;
        }
        __syncthreads();
        int pb = *piv;
        if (pb != k && t < 32) {
            double tmp = aug[k * 32 + t];
            aug[k * 32 + t] = aug[pb * 32 + t];
            aug[pb * 32 + t] = tmp;
        }
        __syncthreads();
        if (t == 0) fs[16] = 1.0 / aug[k * 32 + k];
        __syncthreads();
        if (t < 32) aug[k * 32 + t] *= fs[16];
        __syncthreads();
        if (t < 16) fs[t] = aug[t * 32 + k];
        __syncthreads();
        for (int i = t; i < 512; i += TB) {
            int r = i >> 5, cc = i & 31;
            if (r != k) aug[i] -= fs[r] * aug[k * 32 + cc];
        }
        __syncthreads();
    }
    for (int i = t; i < 256; i += TB) Mout[i] = aug[(i >> 4) * 32 + 16 + (i & 15)];
    __syncthreads();
}

__device__ void matmul16d(const double* A, const double* Bm, double* Cc, int m) {
    const int t = threadIdx.x;
    for (int i = t; i < m * 16; i += TB) {
        int r = i >> 4, cc = i & 15;
        double acc = 0.0;
        #pragma unroll
        for (int x = 0; x < 16; ++x) acc += A[r * 16 + x] * Bm[x * 16 + cc];
        Cc[i] = acc;
    }
    __syncthreads();
}

__device__ void gram16d(const double* A, double* W, int m) {
    const int t = threadIdx.x;
    for (int i = t; i < 256; i += TB) {
        int r = i >> 4, cc = i & 15;
        double acc = 0.0;
        for (int x = 0; x < m; ++x) acc += A[x * 16 + r] * A[x * 16 + cc];
        W[i] = acc;
    }
    __syncthreads();
}

__device__ void vdvtd(const double* V, const double* g, double* P) {
    const int t = threadIdx.x;
    for (int i = t; i < 256; i += TB) {
        int r = i >> 4, cc = i & 15;
        double acc = 0.0;
        #pragma unroll
        for (int x = 0; x < 16; ++x) acc += V[r * 16 + x] * g[x] * V[cc * 16 + x];
        P[i] = acc;
    }
    __syncthreads();
}

// ================= kernels =================

// K1 (warp-per-instance): x_log = log_map(X[0,c], X[b,c]) -> gXlog[bc]
__global__ void __launch_bounds__(TB) k1_logmap(const float* __restrict__ X) {
    __shared__ double UTd[WPB][512];   // U (fp32 view) -> later T1d(256 dbl)+sd(16 dbl)
    __shared__ float Zb[WPB][1024];
    __shared__ float Mm[WPB][272];     // stride-17 16x16
    __shared__ float Ww[WPB][288];
    __shared__ float Vv[WPB][288];
    const int w = threadIdx.x >> 5, lane = threadIdx.x & 31;
    const int bc = blockIdx.x * WPB + w;
    const int c = bc & (Csz - 1);
    float* U = (float*)UTd[w];
    float* Z = Zb[w];
    float* M = Mm[w];
    float* W = Ww[w];
    float* V = Vv[w];
    const float* Xp = X + (size_t)bc * 1024;
    const float* Up = X + (size_t)c * 1024;   // b = 0
    for (int i = lane; i < 1024; i += 32) { U[i] = Up[i]; Z[i] = Xp[i]; }
    __syncwarp();
    // M = U^T X (stride 17)
    for (int i = lane; i < 256; i += 32) {
        int r = i >> 4, cc = i & 15;
        float acc = 0.f;
        for (int x = 0; x < 64; ++x) acc += U[x * 16 + r] * Z[x * 16 + cc];
        M[r * S17 + cc] = acc;
    }
    __syncwarp();
    // Z = Z - U M
    for (int i = lane; i < 1024; i += 32) {
        int r = i >> 4, cc = i & 15;
        float acc = Z[i];
        #pragma unroll
        for (int x = 0; x < 16; ++x) acc -= U[r * 16 + x] * M[x * S17 + cc];
        Z[i] = acc;
    }
    __syncwarp();
    // W = M M^T (bounded)
    for (int i = lane; i < 256; i += 32) {
        int r = i >> 4, cc = i & 15;
        float acc = 0.f;
        #pragma unroll
        for (int x = 0; x < 16; ++x) acc += M[r * S17 + x] * M[cc * S17 + x];
        W[r * S17 + cc] = acc;
    }
    for (int i = lane; i < 288; i += 32) V[i] = 0.f;
    __syncwarp();
    if (lane < 16) V[lane * S17 + lane] = 1.f;
    jacobi_warp(W, V, lane, SWEEPS, true);
    // T1 = M^T V (fp64) into U's storage (U dead)
    double* T1d = UTd[w];
    double* sd = UTd[w] + 256;
    for (int i = lane; i < 256; i += 32) {
        int r = i >> 4, cc = i & 15;
        double acc = 0.0;
        #pragma unroll
        for (int x = 0; x < 16; ++x)
            acc += (double)M[x * S17 + r] * (double)V[x * S17 + cc];
        T1d[i] = acc;
    }
    __syncwarp();
    // Rayleigh lambda + folded scale: gamma_j = alpha_j / sqrt(lam_j)
    if (lane < 16) {
        double lh = 0.0, nr = 0.0;
        #pragma unroll
        for (int i2 = 0; i2 < 16; ++i2) {
            double a = T1d[i2 * 16 + lane]; lh += a * a;
            double v = (double)V[i2 * S17 + lane]; nr += v * v;
        }
        double lam = fmax(lh / nr, 1e-30);
        double om = fmax(1.0 - lam, 0.0);
        double alpha = (om < 1e-28) ? 1.0 : atan(sqrt(om / lam)) / sqrt(om);
        sd[lane] = alpha / sqrt(lam);
    }
    __syncwarp();
    // Ts (bounded) into M
    for (int i = lane; i < 256; i += 32)
        M[(i >> 4) * S17 + (i & 15)] = (float)(T1d[i] * sd[i & 15]);
    __syncwarp();
    // G = Ts V^T into W
    for (int i = lane; i < 256; i += 32) {
        int r = i >> 4, cc = i & 15;
        float acc = 0.f;
        #pragma unroll
        for (int x = 0; x < 16; ++x) acc += M[r * S17 + x] * V[cc * S17 + x];
        W[r * S17 + cc] = acc;
    }
    __syncwarp();
    // x_log = Z G -> gXlog
    float* dst = gXlog + (size_t)bc * 1024;
    for (int i = lane; i < 1024; i += 32) {
        int r = i >> 4, cc = i & 15;
        float acc = 0.f;
        #pragma unroll
        for (int x = 0; x < 16; ++x) acc += Z[r * 16 + x] * W[x * S17 + cc];
        dst[i] = acc;
    }
}

// K2 (per channel, fp64): reduce x_log, exp_map mean, Bm, GinvC
__global__ void k2_mean(const float* __restrict__ X, float* __restrict__ meanOut) {
    __shared__ double Dm[1024], U0[1024], meanS[1024], Cm[768];
    __shared__ double W[256], V[256], M1[256], M2[256], aug[512];
    __shared__ double g[32], cs[16], fs[18];
    __shared__ int piv;
    const int c = blockIdx.x;
    const int t = threadIdx.x;
    for (int i = t; i < 1024; i += TB) {
        double acc = 0.0;
        for (int b = 0; b < Bsz; ++b)
            acc += (double)gXlog[((size_t)b * Csz + c) * 1024 + i];
        Dm[i] = acc * (1.0 / (double)Bsz);
        U0[i] = (double)X[(size_t)c * 1024 + i];
    }
    __syncthreads();
    gram16d(Dm, W, 64);
    jacobi16d(W, V, cs);
    if (t < 16) {
        double S = sqrt(fmax(W[t * 17], 0.0));
        g[t] = cos(S);
        g[16 + t] = (S > 1e-100) ? sin(S) / S : 1.0;
    }
    __syncthreads();
    vdvtd(V, g, M1);
    vdvtd(V, g + 16, M2);
    for (int i = t; i < 1024; i += TB) {
        int r = i >> 4, cc = i & 15;
        double acc = 0.0;
        #pragma unroll
        for (int x = 0; x < 16; ++x)
            acc += U0[r * 16 + x] * M1[x * 16 + cc] + Dm[r * 16 + x] * M2[x * 16 + cc];
        meanS[i] = acc;
        meanOut[c * 1024 + i] = (float)acc;
    }
    __syncthreads();
    invert16d(meanS, aug, M1, fs, &piv);
    matmul16d(meanS + 256, M1, Cm, 48);
    gram16d(Cm, W, 48);
    jacobi16d(W, V, cs);
    if (t < 16) {
        double S = sqrt(fmax(W[t * 17], 0.0));
        g[t] = (S > 1e-100) ? atan(S) / S : 1.0;
    }
    __syncthreads();
    vdvtd(V, g, M2);
    matmul16d(Cm, M2, Dm, 48);
    for (int i = t; i < 768; i += TB) gBmF[c * 768 + i] = (float)Dm[i];
    __syncthreads();
    gram16d(Dm, W, 48);
    for (int i = t; i < 256; i += TB) {
        int r = i >> 4, cc = i & 15;
        W[i] = 0.25 * W[i] + ((r == cc) ? 1.0 : 0.0);
    }
    __syncthreads();
    invert16d(W, aug, M1, fs, &piv);
    for (int i = t; i < 256; i += TB) gGinvCF[c * 256 + i] = (float)M1[i];
}

// K3 (warp-per-instance): theta^2 sum -> gTheta[bc]
__global__ void __launch_bounds__(TB) k3_theta(const float* __restrict__ X,
                                               const float* __restrict__ meanIn) {
    __shared__ float Mn[WPB][1024], Xb[WPB][1024];
    __shared__ float Mm[WPB][272], Ww[WPB][288];
    const int w = threadIdx.x >> 5, lane = threadIdx.x & 31;
    const int bc = blockIdx.x * WPB + w;
    const int c = bc & (Csz - 1);
    float* A = Mn[w];
    float* Xl = Xb[w];
    float* M = Mm[w];
    float* W = Ww[w];
    const float* Xp = X + (size_t)bc * 1024;
    const float* Mp = meanIn + (size_t)c * 1024;
    for (int i = lane; i < 1024; i += 32) { A[i] = Mp[i]; Xl[i] = Xp[i]; }
    __syncwarp();
    for (int i = lane; i < 256; i += 32) {           // M = mean^T X
        int r = i >> 4, cc = i & 15;
        float acc = 0.f;
        for (int x = 0; x < 64; ++x) acc += A[x * 16 + r] * Xl[x * 16 + cc];
        M[r * S17 + cc] = acc;
    }
    __syncwarp();
    for (int i = lane; i < 256; i += 32) {           // W = M^T M
        int r = i >> 4, cc = i & 15;
        float acc = 0.f;
        #pragma unroll
        for (int x = 0; x < 16; ++x) acc += M[x * S17 + r] * M[x * S17 + cc];
        W[r * S17 + cc] = acc;
    }
    jacobi_warp(W, (float*)0, lane, SWEEPS_NV, false);
    if (lane == 0) {
        float sum = 0.f;
        for (int j2 = 0; j2 < 16; ++j2) {
            float s = sqrtf(fmaxf(W[j2 * 18], 0.f));
            s = fminf(s, 1.f);
            float th = acosf(s);
            sum += th * th;
        }
        gTheta[bc] = sum;
    }
}

// K4 (single block): var reduction -> factor; bias Cayley Ginv
__global__ void k4_factor(const float* __restrict__ bias, const float* __restrict__ shiftp) {
    __shared__ double Bb[768], W[256], M1[256], aug[512], fs[18];
    __shared__ int piv;
    const int t = threadIdx.x;
    if (t < Csz) {
        float acc = 0.f;
        for (int b = 0; b < Bsz; ++b) acc += gTheta[b * Csz + t];
        double var = (double)acc * (1.0 / (double)Bsz);
        gFactorF[t] = (float)((double)shiftp[0] / sqrt(var + 1e-5));
    }
    for (int i = t; i < 768; i += TB) Bb[i] = (double)bias[i];
    __syncthreads();
    gram16d(Bb, W, 48);
    for (int i = t; i < 256; i += TB) {
        int r = i >> 4, cc = i & 15;
        W[i] = 0.25 * W[i] + ((r == cc) ? 1.0 : 0.0);
    }
    __syncthreads();
    invert16d(W, aug, M1, fs, &piv);
    for (int i = t; i < 256; i += TB) gGinvBF[i] = (float)M1[i];
}

// K5 (warp-per-instance): center -> gyro scale -> bias
__global__ void __launch_bounds__(TB) k5_final(const float* __restrict__ X,
                                               const float* __restrict__ bias,
                                               float* __restrict__ out) {
    __shared__ float Xs[WPB][1024];
    __shared__ float Bmw[WPB][768];
    __shared__ double bufd[WPB][256];   // Ginv(f) -> W(f,288) ... wait: W needs 288f=1152B <= 2048B OK
    __shared__ float Vv[WPB][288];
    __shared__ float Tt[WPB][256];
    __shared__ double sdk[WPB][16];
    __shared__ float gk[WPB][16];
    const int w = threadIdx.x >> 5, lane = threadIdx.x & 31;
    const int bc = blockIdx.x * WPB + w;
    const int c = bc & (Csz - 1);
    float* Xw = Xs[w];
    float* Bw = Bmw[w];
    float* buf_f = (float*)bufd[w];     // 512 floats of storage
    double* T1d = bufd[w];
    float* V = Vv[w];
    float* T = Tt[w];
    const float* Xp = X + (size_t)bc * 1024;
    for (int i = lane; i < 1024; i += 32) Xw[i] = Xp[i];
    for (int i = lane; i < 768; i += 32) Bw[i] = gBmF[c * 768 + i];
    for (int i = lane; i < 256; i += 32) buf_f[i] = gGinvCF[c * 256 + i]; // Ginv
    __syncwarp();
    // --- Step A: centering Cayley ---
    for (int i = lane; i < 256; i += 32) {
        int r = i >> 4, cc = i & 15;
        float acc = Xw[i];
        for (int k = 0; k < 48; ++k)
            acc += 0.5f * Bw[k * 16 + r] * Xw[256 + k * 16 + cc];
        T[i] = acc;
    }
    __syncwarp();
    {   // Y = Ginv*T staged in regs, then overwrite T
        float yreg[8];
        #pragma unroll
        for (int ii = 0; ii < 8; ++ii) {
            int i = lane + 32 * ii, r = i >> 4, cc = i & 15;
            float acc = 0.f;
            #pragma unroll
            for (int x = 0; x < 16; ++x) acc += buf_f[r * 16 + x] * T[x * 16 + cc];
            yreg[ii] = acc;
        }
        __syncwarp();
        #pragma unroll
        for (int ii = 0; ii < 8; ++ii) T[lane + 32 * ii] = yreg[ii];
    }
    __syncwarp();
    for (int i = lane; i < 1024; i += 32) {
        if (i < 256) Xw[i] = 2.f * T[i] - Xw[i];
        else {
            int r = (i - 256) >> 4, cc = i & 15;
            float acc = Xw[i];
            #pragma unroll
            for (int x = 0; x < 16; ++x) acc -= Bw[r * 16 + x] * T[x * 16 + cc];
            Xw[i] = acc;
        }
    }
    __syncwarp();
    // --- Step B: gyro scaling via K = Xu Xu^T ---
    float* W = buf_f;   // 288 floats (Ginv dead; bufd holds 512 floats)
    for (int i = lane; i < 256; i += 32) {
        int r = i >> 4, cc = i & 15;
        float acc = 0.f;
        #pragma unroll
        for (int x = 0; x < 16; ++x) acc += Xw[r * 16 + x] * Xw[cc * 16 + x];
        W[r * S17 + cc] = acc;
    }
    for (int i = lane; i < 288; i += 32) V[i] = 0.f;
    __syncwarp();
    if (lane < 16) V[lane * S17 + lane] = 1.f;
    jacobi_warp(W, V, lane, SWEEPS, true);
    // T1 = Xu^T V (fp64) into bufd (W dead)
    for (int i = lane; i < 256; i += 32) {
        int r = i >> 4, cc = i & 15;
        double acc = 0.0;
        #pragma unroll
        for (int x = 0; x < 16; ++x)
            acc += (double)Xw[x * 16 + r] * (double)V[x * S17 + cc];
        T1d[i] = acc;
    }
    __syncwarp();
    float fct = gFactorF[c];
    if (lane < 16) {
        double lh = 0.0, nr = 0.0;
        #pragma unroll
        for (int i2 = 0; i2 < 16; ++i2) {
            double a = T1d[i2 * 16 + lane]; lh += a * a;
            double v = (double)V[i2 * S17 + lane]; nr += v * v;
        }
        double lam = fmax(lh / nr, 1e-30);
        double om = fmax(1.0 - lam, 0.0);
        double beta, cth;
        if (om < 1e-28) { beta = (double)fct; cth = 1.0; }
        else {
            double th = (double)fct * atan(sqrt(om / lam));
            beta = sin(th) / sqrt(om);
            cth = cos(th);
        }
        sdk[w][lane] = beta / sqrt(lam);
        gk[w][lane] = (float)cth;
    }
    __syncwarp();
    {   // Tsf (bounded) staged in regs, then into buf_f[0..255]
        float treg[8];
        #pragma unroll
        for (int ii = 0; ii < 8; ++ii) {
            int i = lane + 32 * ii;
            treg[ii] = (float)(T1d[i] * sdk[w][i & 15]);
        }
        __syncwarp();
        #pragma unroll
        for (int ii = 0; ii < 8; ++ii) buf_f[lane + 32 * ii] = treg[ii];
    }
    __syncwarp();
    float* Tsf = buf_f;          // 256f
    float* M2f = buf_f + 256;    // 256f
    for (int i = lane; i < 256; i += 32) {   // M2 = Tsf V^T
        int r = i >> 4, cc = i & 15;
        float acc = 0.f;
        #pragma unroll
        for (int x = 0; x < 16; ++x) acc += Tsf[r * 16 + x] * V[cc * S17 + x];
        M2f[i] = acc;
    }
    __syncwarp();
    for (int i = lane; i < 256; i += 32) {   // top = V cos V^T into T
        int r = i >> 4, cc = i & 15;
        float acc = 0.f;
        #pragma unroll
        for (int x = 0; x < 16; ++x) acc += V[r * S17 + x] * gk[w][x] * V[cc * S17 + x];
        T[i] = acc;
    }
    for (int i = lane; i < 768; i += 32) {   // bot = Xl M2 into Bw (dead)
        int r = i >> 4, cc = i & 15;
        float acc = 0.f;
        #pragma unroll
        for (int x = 0; x < 16; ++x) acc += Xw[256 + r * 16 + x] * M2f[x * 16 + cc];
        Bw[i] = acc;
    }
    __syncwarp();
    for (int i = lane; i < 256; i += 32) Xw[i] = T[i];
    for (int i = lane; i < 768; i += 32) Xw[256 + i] = Bw[i];
    __syncwarp();
    // --- Step C: bias Cayley ---
    for (int i = lane; i < 768; i += 32) Bw[i] = bias[i];
    for (int i = lane; i < 256; i += 32) buf_f[i] = gGinvBF[i];  // Ginv
    __syncwarp();
    for (int i = lane; i < 256; i += 32) {
        int r = i >> 4, cc = i & 15;
        float acc = Xw[i];
        for (int k = 0; k < 48; ++k)
            acc -= 0.5f * Bw[k * 16 + r] * Xw[256 + k * 16 + cc];
        T[i] = acc;
    }
    __syncwarp();
    {   // Y = Ginv*T staged
        float yreg[8];
        #pragma unroll
        for (int ii = 0; ii < 8; ++ii) {
            int i = lane + 32 * ii, r = i >> 4, cc = i & 15;
            float acc = 0.f;
            #pragma unroll
            for (int x = 0; x < 16; ++x) acc += buf_f[r * 16 + x] * T[x * 16 + cc];
            yreg[ii] = acc;
        }
        __syncwarp();
        #pragma unroll
        for (int ii = 0; ii < 8; ++ii) T[lane + 32 * ii] = yreg[ii];
    }
    __syncwarp();
    float* dst = out + (size_t)bc * 1024;
    for (int i = lane; i < 1024; i += 32) {
        if (i < 256) dst[i] = 2.f * T[i] - Xw[i];
        else {
            int r = (i - 256) >> 4, cc = i & 15;
            float acc = Xw[i];
            #pragma unroll
            for (int x = 0; x < 16; ++x) acc += Bw[r * 16 + x] * T[x * 16 + cc];
            dst[i] = acc;
        }
    }
}

// ---------------- launch ----------------
extern "C" void kernel_launch(void* const* d_in, const int* in_sizes, int n_in,
                              void* d_out, int out_size) {
    const float* X = (const float*)d_in[0];
    const float* bias = (const float*)d_in[1];
    const float* shift = (const float*)d_in[2];
    float* out = (float*)d_out;
    float* meanOut = out + (size_t)Bsz * Csz * Nsz * Psz;

    const int nInst = Bsz * Csz;
    k1_logmap<<<nInst / WPB, TB>>>(X);
    k2_mean<<<Csz, TB>>>(X, meanOut);
    k3_theta<<<nInst / WPB, TB>>>(X, meanOut);
    k4_factor<<<1, TB>>>(bias, shift);
    k5_final<<<nInst / WPB, TB>>>(X, bias, out);
}

// round 7
// speedup vs baseline: 19.0708x; 1.0249x over previous
#include <cuda_runtime.h>

#define Bsz 256
#define Csz 128
#define Nsz 64
#define Psz 16
#define Qsz 48
#define TB 128
#define WPB 4
#define SWEEPS_W 6
#define SWEEPS_NV 5
#define SWEEPS_D 5
#define S17 17

// ---------------- device scratch (static, no allocations) ----------------
__device__ alignas(16) float gXlog[(size_t)Bsz * Csz * Nsz * Psz]; // 128MB
__device__ float gTheta[Bsz * Csz];
__device__ alignas(16) float gBmF[Csz * Qsz * Psz];
__device__ alignas(16) float gGinvCF[Csz * Psz * Psz];
__device__ alignas(16) float gGinvBF[Psz * Psz];
__device__ float gFactorF[Csz];

// ================= warp-level Jacobi =================
__device__ __forceinline__ void jacobi_warp(float* W, float* V, int lane,
                                            int sweeps, bool wantV) {
    const int j = lane >> 2;
    const int b4 = (lane & 3) * 4;
    for (int sweep = 0; sweep < sweeps; ++sweep) {
        for (int r = 0; r < 15; ++r) {
            int p, q;
            if (j == 0) { p = 15; q = r; }
            else { p = (r + j) % 15; q = (r + 15 - j) % 15; }
            if (p < q) { int tmp = p; p = q; q = tmp; }
            __syncwarp();
            float c = 1.f, s = 0.f;
            if ((lane & 3) == 0) {
                float app = W[p * S17 + p], aqq = W[q * S17 + q], apq = W[p * S17 + q];
                if (fabsf(apq) > 1e-37f) {
                    float tau = (aqq - app) / (2.f * apq);
                    float tt = copysignf(1.f, tau) / (fabsf(tau) + sqrtf(1.f + tau * tau));
                    c = rsqrtf(1.f + tt * tt);
                    s = tt * c;
                }
            }
            c = __shfl_sync(0xffffffffu, c, lane & ~3);
            s = __shfl_sync(0xffffffffu, s, lane & ~3);
            #pragma unroll
            for (int k = 0; k < 4; ++k) {
                int col = b4 + k;
                float wp = W[p * S17 + col], wq = W[q * S17 + col];
                W[p * S17 + col] = c * wp - s * wq;
                W[q * S17 + col] = s * wp + c * wq;
            }
            __syncwarp();
            #pragma unroll
            for (int k = 0; k < 4; ++k) {
                int row = b4 + k;
                float xp = W[row * S17 + p], xq = W[row * S17 + q];
                W[row * S17 + p] = c * xp - s * xq;
                W[row * S17 + q] = s * xp + c * xq;
                if (wantV) {
                    float vp = V[row * S17 + p], vq = V[row * S17 + q];
                    V[row * S17 + p] = c * vp - s * vq;
                    V[row * S17 + q] = s * vp + c * vq;
                }
            }
        }
    }
    __syncwarp();
}

// ================= block-level fp64 helpers (k2/k4) =================
__device__ void jacobi16d(double* W, double* V, double* cs) {
    const int t = threadIdx.x;
    for (int i = t; i < 256; i += TB) V[i] = ((i >> 4) == (i & 15)) ? 1.0 : 0.0;
    __syncthreads();
    const int pr = t >> 4, el = t & 15;
    for (int sweep = 0; sweep < SWEEPS_D; ++sweep) {
        for (int r = 0; r < 15; ++r) {
            int p, q;
            if (pr == 0) { p = 15; q = r; }
            else { p = (r + pr) % 15; q = (r + 15 - pr) % 15; }
            if (p < q) { int tmp = p; p = q; q = tmp; }
            if (el == 0) {
                double app = W[p * 16 + p], aqq = W[q * 16 + q], apq = W[p * 16 + q];
                double c = 1.0, s = 0.0;
                if (fabs(apq) > 1e-300) {
                    double tau = (aqq - app) / (2.0 * apq);
                    double tt = copysign(1.0, tau) / (fabs(tau) + sqrt(1.0 + tau * tau));
                    c = rsqrt(1.0 + tt * tt);
                    s = tt * c;
                }
                cs[pr] = c; cs[8 + pr] = s;
            }
            __syncthreads();
            double c = cs[pr], s = cs[8 + pr];
            double wp = W[p * 16 + el], wq = W[q * 16 + el];
            W[p * 16 + el] = c * wp - s * wq;
            W[q * 16 + el] = s * wp + c * wq;
            __syncthreads();
            double xp = W[el * 16 + p], xq = W[el * 16 + q];
            W[el * 16 + p] = c * xp - s * xq;
            W[el * 16 + q] = s * xp + c * xq;
            double vp = V[el * 16 + p], vq = V[el * 16 + q];
            V[el * 16 + p] = c * vp - s * vq;
            V[el * 16 + q] = s * vp + c * vq;
            __syncthreads();
        }
    }
}

__device__ void invert16d(const double* Min, double* aug, double* Mout, double* fs, int* piv) {
    const int t = threadIdx.x;
    for (int i = t; i < 512; i += TB) {
        int r = i >> 5, cc = i & 31;
        aug[i] = (cc < 16) ? Min[r * 16 + cc] : ((cc - 16 == r) ? 1.0 : 0.0);
    }
    __syncthreads();
    for (int k = 0; k < 16; ++k) {
        if (t == 0) {
            int best = k; double bv = fabs(aug[k * 32 + k]);
            for (int i = k + 1; i < 16; ++i) {
                double v = fabs(aug[i * 32 + k]);
                if (v > bv) { bv = v; best = i; }
            }
            *piv = best;
        }
        __syncthreads();
        int pb = *piv;
        if (pb != k && t < 32) {
            double tmp = aug[k * 32 + t];
            aug[k * 32 + t] = aug[pb * 32 + t];
            aug[pb * 32 + t] = tmp;
        }
        __syncthreads();
        if (t == 0) fs[16] = 1.0 / aug[k * 32 + k];
        __syncthreads();
        if (t < 32) aug[k * 32 + t] *= fs[16];
        __syncthreads();
        if (t < 16) fs[t] = aug[t * 32 + k];
        __syncthreads();
        for (int i = t; i < 512; i += TB) {
            int r = i >> 5, cc = i & 31;
            if (r != k) aug[i] -= fs[r] * aug[k * 32 + cc];
        }
        __syncthreads();
    }
    for (int i = t; i < 256; i += TB) Mout[i] = aug[(i >> 4) * 32 + 16 + (i & 15)];
    __syncthreads();
}

__device__ void matmul16d(const double* A, const double* Bm, double* Cc, int m) {
    const int t = threadIdx.x;
    for (int i = t; i < m * 16; i += TB) {
        int r = i >> 4, cc = i & 15;
        double acc = 0.0;
        #pragma unroll
        for (int x = 0; x < 16; ++x) acc += A[r * 16 + x] * Bm[x * 16 + cc];
        Cc[i] = acc;
    }
    __syncthreads();
}

__device__ void gram16d(const double* A, double* W, int m) {
    const int t = threadIdx.x;
    for (int i = t; i < 256; i += TB) {
        int r = i >> 4, cc = i & 15;
        double acc = 0.0;
        for (int x = 0; x < m; ++x) acc += A[x * 16 + r] * A[x * 16 + cc];
        W[i] = acc;
    }
    __syncthreads();
}

__device__ void vdvtd(const double* V, const double* g, double* P) {
    const int t = threadIdx.x;
    for (int i = t; i < 256; i += TB) {
        int r = i >> 4, cc = i & 15;
        double acc = 0.0;
        #pragma unroll
        for (int x = 0; x < 16; ++x) acc += V[r * 16 + x] * g[x] * V[cc * 16 + x];
        P[i] = acc;
    }
    __syncthreads();
}

// ================= kernels =================

// K1 (warp-per-instance): x_log = log_map(X[0,c], X[b,c]) -> gXlog[bc]
__global__ void __launch_bounds__(TB) k1_logmap(const float* __restrict__ X) {
    __shared__ alignas(16) double UTd[WPB][512];
    __shared__ alignas(16) float Zb[WPB][1024];
    __shared__ float Mm[WPB][272];
    __shared__ float Ww[WPB][288];
    __shared__ float Vv[WPB][288];
    const int w = threadIdx.x >> 5, lane = threadIdx.x & 31;
    const int bc = blockIdx.x * WPB + w;
    const int c = bc & (Csz - 1);
    float* U = (float*)UTd[w];
    float* Z = Zb[w];
    float* M = Mm[w];
    float* W = Ww[w];
    float* V = Vv[w];
    const float4* Xp4 = (const float4*)(X + (size_t)bc * 1024);
    const float4* Up4 = (const float4*)(X + (size_t)c * 1024);
    float4* U4 = (float4*)U;
    float4* Z4 = (float4*)Z;
    for (int i = lane; i < 256; i += 32) { U4[i] = Up4[i]; Z4[i] = Xp4[i]; }
    __syncwarp();
    // M = U^T X
    for (int i = lane; i < 256; i += 32) {
        int r = i >> 4, cc = i & 15;
        float acc = 0.f;
        for (int x = 0; x < 64; ++x) acc += U[x * 16 + r] * Z[x * 16 + cc];
        M[r * S17 + cc] = acc;
    }
    __syncwarp();
    // Z = Z - U M
    for (int i = lane; i < 1024; i += 32) {
        int r = i >> 4, cc = i & 15;
        float acc = Z[i];
        #pragma unroll
        for (int x = 0; x < 16; ++x) acc -= U[r * 16 + x] * M[x * S17 + cc];
        Z[i] = acc;
    }
    __syncwarp();
    // W = M M^T (bounded)
    for (int i = lane; i < 256; i += 32) {
        int r = i >> 4, cc = i & 15;
        float acc = 0.f;
        #pragma unroll
        for (int x = 0; x < 16; ++x) acc += M[r * S17 + x] * M[cc * S17 + x];
        W[r * S17 + cc] = acc;
    }
    for (int i = lane; i < 288; i += 32) V[i] = 0.f;
    __syncwarp();
    if (lane < 16) V[lane * S17 + lane] = 1.f;
    jacobi_warp(W, V, lane, SWEEPS_W, true);
    // T1 = M^T V (fp64) into U's storage (U dead)
    double* T1d = UTd[w];
    double* sd = UTd[w] + 256;
    for (int i = lane; i < 256; i += 32) {
        int r = i >> 4, cc = i & 15;
        double acc = 0.0;
        #pragma unroll
        for (int x = 0; x < 16; ++x)
            acc += (double)M[x * S17 + r] * (double)V[x * S17 + cc];
        T1d[i] = acc;
    }
    __syncwarp();
    if (lane < 16) {
        double lh = 0.0, nr = 0.0;
        #pragma unroll
        for (int i2 = 0; i2 < 16; ++i2) {
            double a = T1d[i2 * 16 + lane]; lh += a * a;
            double v = (double)V[i2 * S17 + lane]; nr += v * v;
        }
        double lam = fmax(lh / nr, 1e-30);
        double om = fmax(1.0 - lam, 0.0);
        double alpha = (om < 1e-28) ? 1.0 : atan(sqrt(om / lam)) / sqrt(om);
        sd[lane] = alpha / sqrt(lam);
    }
    __syncwarp();
    for (int i = lane; i < 256; i += 32)
        M[(i >> 4) * S17 + (i & 15)] = (float)(T1d[i] * sd[i & 15]);
    __syncwarp();
    // G = Ts V^T into W
    for (int i = lane; i < 256; i += 32) {
        int r = i >> 4, cc = i & 15;
        float acc = 0.f;
        #pragma unroll
        for (int x = 0; x < 16; ++x) acc += M[r * S17 + x] * V[cc * S17 + x];
        W[r * S17 + cc] = acc;
    }
    __syncwarp();
    // x_log = Z G -> gXlog (vectorized 4-wide)
    float4* dst4 = (float4*)(gXlog + (size_t)bc * 1024);
    for (int i4 = lane; i4 < 256; i4 += 32) {
        int r = i4 >> 2, cb = (i4 & 3) * 4;
        float a0 = 0.f, a1 = 0.f, a2 = 0.f, a3 = 0.f;
        #pragma unroll
        for (int x = 0; x < 16; ++x) {
            float z = Z[r * 16 + x];
            a0 += z * W[x * S17 + cb];
            a1 += z * W[x * S17 + cb + 1];
            a2 += z * W[x * S17 + cb + 2];
            a3 += z * W[x * S17 + cb + 3];
        }
        dst4[i4] = make_float4(a0, a1, a2, a3);
    }
}

// K2 (per channel, fp64): reduce x_log, exp_map mean, Bm, GinvC
__global__ void k2_mean(const float* __restrict__ X, float* __restrict__ meanOut) {
    __shared__ double Dm[1024], U0[1024], meanS[1024], Cm[768];
    __shared__ double W[256], V[256], M1[256], M2[256], aug[512];
    __shared__ double g[32], cs[16], fs[18];
    __shared__ int piv;
    const int c = blockIdx.x;
    const int t = threadIdx.x;
    const float4* gX4 = (const float4*)gXlog;
    for (int i4 = t; i4 < 256; i4 += TB) {
        double a0 = 0.0, a1 = 0.0, a2 = 0.0, a3 = 0.0;
        #pragma unroll 4
        for (int b = 0; b < Bsz; ++b) {
            float4 v = gX4[((size_t)b * Csz + c) * 256 + i4];
            a0 += v.x; a1 += v.y; a2 += v.z; a3 += v.w;
        }
        const double inv = 1.0 / (double)Bsz;
        int i = i4 * 4;
        Dm[i] = a0 * inv; Dm[i + 1] = a1 * inv; Dm[i + 2] = a2 * inv; Dm[i + 3] = a3 * inv;
    }
    for (int i = t; i < 1024; i += TB)
        U0[i] = (double)X[(size_t)c * 1024 + i];
    __syncthreads();
    gram16d(Dm, W, 64);
    jacobi16d(W, V, cs);
    if (t < 16) {
        double S = sqrt(fmax(W[t * 17], 0.0));
        g[t] = cos(S);
        g[16 + t] = (S > 1e-100) ? sin(S) / S : 1.0;
    }
    __syncthreads();
    vdvtd(V, g, M1);
    vdvtd(V, g + 16, M2);
    for (int i = t; i < 1024; i += TB) {
        int r = i >> 4, cc = i & 15;
        double acc = 0.0;
        #pragma unroll
        for (int x = 0; x < 16; ++x)
            acc += U0[r * 16 + x] * M1[x * 16 + cc] + Dm[r * 16 + x] * M2[x * 16 + cc];
        meanS[i] = acc;
        meanOut[c * 1024 + i] = (float)acc;
    }
    __syncthreads();
    invert16d(meanS, aug, M1, fs, &piv);
    matmul16d(meanS + 256, M1, Cm, 48);
    gram16d(Cm, W, 48);
    jacobi16d(W, V, cs);
    if (t < 16) {
        double S = sqrt(fmax(W[t * 17], 0.0));
        g[t] = (S > 1e-100) ? atan(S) / S : 1.0;
    }
    __syncthreads();
    vdvtd(V, g, M2);
    matmul16d(Cm, M2, Dm, 48);
    for (int i = t; i < 768; i += TB) gBmF[c * 768 + i] = (float)Dm[i];
    __syncthreads();
    gram16d(Dm, W, 48);
    for (int i = t; i < 256; i += TB) {
        int r = i >> 4, cc = i & 15;
        W[i] = 0.25 * W[i] + ((r == cc) ? 1.0 : 0.0);
    }
    __syncthreads();
    invert16d(W, aug, M1, fs, &piv);
    for (int i = t; i < 256; i += TB) gGinvCF[c * 256 + i] = (float)M1[i];
}

// K3 (warp-per-instance): theta^2 sum -> gTheta[bc]
__global__ void __launch_bounds__(TB) k3_theta(const float* __restrict__ X,
                                               const float* __restrict__ meanIn) {
    __shared__ alignas(16) float Mn[WPB][1024];
    __shared__ alignas(16) float Xb[WPB][1024];
    __shared__ float Mm[WPB][272], Ww[WPB][288];
    const int w = threadIdx.x >> 5, lane = threadIdx.x & 31;
    const int bc = blockIdx.x * WPB + w;
    const int c = bc & (Csz - 1);
    float* A = Mn[w];
    float* Xl = Xb[w];
    float* M = Mm[w];
    float* W = Ww[w];
    const float4* Xp4 = (const float4*)(X + (size_t)bc * 1024);
    const float4* Mp4 = (const float4*)(meanIn + (size_t)c * 1024);
    float4* A4 = (float4*)A;
    float4* Xl4 = (float4*)Xl;
    for (int i = lane; i < 256; i += 32) { A4[i] = Mp4[i]; Xl4[i] = Xp4[i]; }
    __syncwarp();
    for (int i = lane; i < 256; i += 32) {
        int r = i >> 4, cc = i & 15;
        float acc = 0.f;
        for (int x = 0; x < 64; ++x) acc += A[x * 16 + r] * Xl[x * 16 + cc];
        M[r * S17 + cc] = acc;
    }
    __syncwarp();
    for (int i = lane; i < 256; i += 32) {
        int r = i >> 4, cc = i & 15;
        float acc = 0.f;
        #pragma unroll
        for (int x = 0; x < 16; ++x) acc += M[x * S17 + r] * M[x * S17 + cc];
        W[r * S17 + cc] = acc;
    }
    jacobi_warp(W, (float*)0, lane, SWEEPS_NV, false);
    if (lane == 0) {
        float sum = 0.f;
        for (int j2 = 0; j2 < 16; ++j2) {
            float s = sqrtf(fmaxf(W[j2 * 18], 0.f));
            s = fminf(s, 1.f);
            float th = acosf(s);
            sum += th * th;
        }
        gTheta[bc] = sum;
    }
}

// K4 (grid=Csz): per-channel factor via tree reduction; block 0 also bias Ginv
__global__ void k4_factor(const float* __restrict__ bias, const float* __restrict__ shiftp) {
    __shared__ float red[TB];
    __shared__ double Bb[768], W[256], M1[256], aug[512], fs[18];
    __shared__ int piv;
    const int t = threadIdx.x;
    const int c = blockIdx.x;
    red[t] = gTheta[t * Csz + c] + gTheta[(t + TB) * Csz + c];
    __syncthreads();
    for (int s = TB / 2; s > 0; s >>= 1) {
        if (t < s) red[t] += red[t + s];
        __syncthreads();
    }
    if (t == 0) {
        double var = (double)red[0] * (1.0 / (double)Bsz);
        gFactorF[c] = (float)((double)shiftp[0] / sqrt(var + 1e-5));
    }
    if (c == 0) {
        for (int i = t; i < 768; i += TB) Bb[i] = (double)bias[i];
        __syncthreads();
        gram16d(Bb, W, 48);
        for (int i = t; i < 256; i += TB) {
            int r = i >> 4, cc = i & 15;
            W[i] = 0.25 * W[i] + ((r == cc) ? 1.0 : 0.0);
        }
        __syncthreads();
        invert16d(W, aug, M1, fs, &piv);
        for (int i = t; i < 256; i += TB) gGinvBF[i] = (float)M1[i];
    }
}

// K5 (warp-per-instance): center -> gyro scale -> bias
__global__ void __launch_bounds__(TB) k5_final(const float* __restrict__ X,
                                               const float* __restrict__ bias,
                                               float* __restrict__ out) {
    __shared__ alignas(16) float Xs[WPB][1024];
    __shared__ alignas(16) float Bmw[WPB][768];
    __shared__ alignas(16) double bufd[WPB][256];
    __shared__ float Vv[WPB][288];
    __shared__ alignas(16) float Tt[WPB][256];
    __shared__ double sdk[WPB][16];
    __shared__ float gk[WPB][16];
    const int w = threadIdx.x >> 5, lane = threadIdx.x & 31;
    const int bc = blockIdx.x * WPB + w;
    const int c = bc & (Csz - 1);
    float* Xw = Xs[w];
    float* Bw = Bmw[w];
    float* buf_f = (float*)bufd[w];
    double* T1d = bufd[w];
    float* V = Vv[w];
    float* T = Tt[w];
    {
        const float4* Xp4 = (const float4*)(X + (size_t)bc * 1024);
        const float4* Bm4 = (const float4*)(gBmF + (size_t)c * 768);
        const float4* Gi4 = (const float4*)(gGinvCF + (size_t)c * 256);
        float4* Xw4 = (float4*)Xw;
        float4* Bw4 = (float4*)Bw;
        float4* bf4 = (float4*)buf_f;
        for (int i = lane; i < 256; i += 32) Xw4[i] = Xp4[i];
        for (int i = lane; i < 192; i += 32) Bw4[i] = Bm4[i];
        for (int i = lane; i < 64; i += 32) bf4[i] = Gi4[i];
    }
    __syncwarp();
    // --- Step A: centering Cayley ---
    for (int i = lane; i < 256; i += 32) {
        int r = i >> 4, cc = i & 15;
        float acc = Xw[i];
        for (int k = 0; k < 48; ++k)
            acc += 0.5f * Bw[k * 16 + r] * Xw[256 + k * 16 + cc];
        T[i] = acc;
    }
    __syncwarp();
    {
        float yreg[8];
        #pragma unroll
        for (int ii = 0; ii < 8; ++ii) {
            int i = lane + 32 * ii, r = i >> 4, cc = i & 15;
            float acc = 0.f;
            #pragma unroll
            for (int x = 0; x < 16; ++x) acc += buf_f[r * 16 + x] * T[x * 16 + cc];
            yreg[ii] = acc;
        }
        __syncwarp();
        #pragma unroll
        for (int ii = 0; ii < 8; ++ii) T[lane + 32 * ii] = yreg[ii];
    }
    __syncwarp();
    for (int i = lane; i < 1024; i += 32) {
        if (i < 256) Xw[i] = 2.f * T[i] - Xw[i];
        else {
            int r = (i - 256) >> 4, cc = i & 15;
            float acc = Xw[i];
            #pragma unroll
            for (int x = 0; x < 16; ++x) acc -= Bw[r * 16 + x] * T[x * 16 + cc];
            Xw[i] = acc;
        }
    }
    __syncwarp();
    // --- Step B: gyro scaling via K = Xu Xu^T ---
    float* W = buf_f;
    for (int i = lane; i < 256; i += 32) {
        int r = i >> 4, cc = i & 15;
        float acc = 0.f;
        #pragma unroll
        for (int x = 0; x < 16; ++x) acc += Xw[r * 16 + x] * Xw[cc * 16 + x];
        W[r * S17 + cc] = acc;
    }
    for (int i = lane; i < 288; i += 32) V[i] = 0.f;
    __syncwarp();
    if (lane < 16) V[lane * S17 + lane] = 1.f;
    jacobi_warp(W, V, lane, SWEEPS_W, true);
    for (int i = lane; i < 256; i += 32) {
        int r = i >> 4, cc = i & 15;
        double acc = 0.0;
        #pragma unroll
        for (int x = 0; x < 16; ++x)
            acc += (double)Xw[x * 16 + r] * (double)V[x * S17 + cc];
        T1d[i] = acc;
    }
    __syncwarp();
    float fct = gFactorF[c];
    if (lane < 16) {
        double lh = 0.0, nr = 0.0;
        #pragma unroll
        for (int i2 = 0; i2 < 16; ++i2) {
            double a = T1d[i2 * 16 + lane]; lh += a * a;
            double v = (double)V[i2 * S17 + lane]; nr += v * v;
        }
        double lam = fmax(lh / nr, 1e-30);
        double om = fmax(1.0 - lam, 0.0);
        double beta, cth;
        if (om < 1e-28) { beta = (double)fct; cth = 1.0; }
        else {
            double th = (double)fct * atan(sqrt(om / lam));
            beta = sin(th) / sqrt(om);
            cth = cos(th);
        }
        sdk[w][lane] = beta / sqrt(lam);
        gk[w][lane] = (float)cth;
    }
    __syncwarp();
    {
        float treg[8];
        #pragma unroll
        for (int ii = 0; ii < 8; ++ii) {
            int i = lane + 32 * ii;
            treg[ii] = (float)(T1d[i] * sdk[w][i & 15]);
        }
        __syncwarp();
        #pragma unroll
        for (int ii = 0; ii < 8; ++ii) buf_f[lane + 32 * ii] = treg[ii];
    }
    __syncwarp();
    float* Tsf = buf_f;
    float* M2f = buf_f + 256;
    for (int i = lane; i < 256; i += 32) {
        int r = i >> 4, cc = i & 15;
        float acc = 0.f;
        #pragma unroll
        for (int x = 0; x < 16; ++x) acc += Tsf[r * 16 + x] * V[cc * S17 + x];
        M2f[i] = acc;
    }
    __syncwarp();
    for (int i = lane; i < 256; i += 32) {
        int r = i >> 4, cc = i & 15;
        float acc = 0.f;
        #pragma unroll
        for (int x = 0; x < 16; ++x) acc += V[r * S17 + x] * gk[w][x] * V[cc * S17 + x];
        T[i] = acc;
    }
    for (int i = lane; i < 768; i += 32) {
        int r = i >> 4, cc = i & 15;
        float acc = 0.f;
        #pragma unroll
        for (int x = 0; x < 16; ++x) acc += Xw[256 + r * 16 + x] * M2f[x * 16 + cc];
        Bw[i] = acc;
    }
    __syncwarp();
    {
        float4* Xw4 = (float4*)Xw;
        float4* T4 = (float4*)T;
        float4* Bw4 = (float4*)Bw;
        for (int i = lane; i < 64; i += 32) Xw4[i] = T4[i];
        for (int i = lane; i < 192; i += 32) Xw4[64 + i] = Bw4[i];
    }
    __syncwarp();
    // --- Step C: bias Cayley ---
    {
        const float4* b4 = (const float4*)bias;
        const float4* g4 = (const float4*)gGinvBF;
        float4* Bw4 = (float4*)Bw;
        float4* bf4 = (float4*)buf_f;
        for (int i = lane; i < 192; i += 32) Bw4[i] = b4[i];
        for (int i = lane; i < 64; i += 32) bf4[i] = g4[i];
    }
    __syncwarp();
    for (int i = lane; i < 256; i += 32) {
        int r = i >> 4, cc = i & 15;
        float acc = Xw[i];
        for (int k = 0; k < 48; ++k)
            acc -= 0.5f * Bw[k * 16 + r] * Xw[256 + k * 16 + cc];
        T[i] = acc;
    }
    __syncwarp();
    {
        float yreg[8];
        #pragma unroll
        for (int ii = 0; ii < 8; ++ii) {
            int i = lane + 32 * ii, r = i >> 4, cc = i & 15;
            float acc = 0.f;
            #pragma unroll
            for (int x = 0; x < 16; ++x) acc += buf_f[r * 16 + x] * T[x * 16 + cc];
            yreg[ii] = acc;
        }
        __syncwarp();
        #pragma unroll
        for (int ii = 0; ii < 8; ++ii) T[lane + 32 * ii] = yreg[ii];
    }
    __syncwarp();
    float4* dst4 = (float4*)(out + (size_t)bc * 1024);
    for (int i4 = lane; i4 < 64; i4 += 32) {
        float4 t4 = ((float4*)T)[i4];
        float4 x4 = ((float4*)Xw)[i4];
        dst4[i4] = make_float4(2.f * t4.x - x4.x, 2.f * t4.y - x4.y,
                               2.f * t4.z - x4.z, 2.f * t4.w - x4.w);
    }
    for (int i4 = lane; i4 < 192; i4 += 32) {
        int r = i4 >> 2, cb = (i4 & 3) * 4;
        float a0 = Xw[256 + r * 16 + cb];
        float a1 = Xw[256 + r * 16 + cb + 1];
        float a2 = Xw[256 + r * 16 + cb + 2];
        float a3 = Xw[256 + r * 16 + cb + 3];
        #pragma unroll
        for (int x = 0; x < 16; ++x) {
            float bv = Bw[r * 16 + x];
            a0 += bv * T[x * 16 + cb];
            a1 += bv * T[x * 16 + cb + 1];
            a2 += bv * T[x * 16 + cb + 2];
            a3 += bv * T[x * 16 + cb + 3];
        }
        dst4[64 + i4] = make_float4(a0, a1, a2, a3);
    }
}

// ---------------- launch ----------------
extern "C" void kernel_launch(void* const* d_in, const int* in_sizes, int n_in,
                              void* d_out, int out_size) {
    const float* X = (const float*)d_in[0];
    const float* bias = (const float*)d_in[1];
    const float* shift = (const float*)d_in[2];
    float* out = (float*)d_out;
    float* meanOut = out + (size_t)Bsz * Csz * Nsz * Psz;

    const int nInst = Bsz * Csz;
    k1_logmap<<<nInst / WPB, TB>>>(X);
    k2_mean<<<Csz, TB>>>(X, meanOut);
    k3_theta<<<nInst / WPB, TB>>>(X, meanOut);
    k4_factor<<<Csz, TB>>>(bias, shift);
    k5_final<<<nInst / WPB, TB>>>(X, bias, out);
}

// round 8
// speedup vs baseline: 23.8179x; 1.2489x over previous
#include <cuda_runtime.h>

#define Bsz 256
#define Csz 128
#define Nsz 64
#define Psz 16
#define Qsz 48
#define TB 128
#define WPB 4
#define SWEEPS_W 6
#define SWEEPS_NV 5
#define SWEEPS_D 5
#define S17 17

// ---------------- device scratch (static, no allocations) ----------------
__device__ alignas(16) float gXlog[(size_t)Bsz * Csz * Nsz * Psz]; // 128MB
__device__ float gTheta[Bsz * Csz];
__device__ alignas(16) float gBmF[Csz * Qsz * Psz];
__device__ alignas(16) float gGinvCF[Csz * Psz * Psz];
__device__ alignas(16) float gGinvBF[Psz * Psz];
__device__ float gFactorF[Csz];

// ================= warp-level Jacobi =================
__device__ __forceinline__ void jacobi_warp(float* W, float* V, int lane,
                                            int sweeps, bool wantV) {
    const int j = lane >> 2;
    const int b4 = (lane & 3) * 4;
    for (int sweep = 0; sweep < sweeps; ++sweep) {
        for (int r = 0; r < 15; ++r) {
            int p, q;
            if (j == 0) { p = 15; q = r; }
            else { p = (r + j) % 15; q = (r + 15 - j) % 15; }
            if (p < q) { int tmp = p; p = q; q = tmp; }
            __syncwarp();
            float c = 1.f, s = 0.f;
            if ((lane & 3) == 0) {
                float app = W[p * S17 + p], aqq = W[q * S17 + q], apq = W[p * S17 + q];
                if (fabsf(apq) > 1e-37f) {
                    float tau = (aqq - app) / (2.f * apq);
                    float tt = copysignf(1.f, tau) / (fabsf(tau) + sqrtf(1.f + tau * tau));
                    c = rsqrtf(1.f + tt * tt);
                    s = tt * c;
                }
            }
            c = __shfl_sync(0xffffffffu, c, lane & ~3);
            s = __shfl_sync(0xffffffffu, s, lane & ~3);
            #pragma unroll
            for (int k = 0; k < 4; ++k) {
                int col = b4 + k;
                float wp = W[p * S17 + col], wq = W[q * S17 + col];
                W[p * S17 + col] = c * wp - s * wq;
                W[q * S17 + col] = s * wp + c * wq;
            }
            __syncwarp();
            #pragma unroll
            for (int k = 0; k < 4; ++k) {
                int row = b4 + k;
                float xp = W[row * S17 + p], xq = W[row * S17 + q];
                W[row * S17 + p] = c * xp - s * xq;
                W[row * S17 + q] = s * xp + c * xq;
                if (wantV) {
                    float vp = V[row * S17 + p], vq = V[row * S17 + q];
                    V[row * S17 + p] = c * vp - s * vq;
                    V[row * S17 + q] = s * vp + c * vq;
                }
            }
        }
    }
    __syncwarp();
}

// ================= block-level fp64 helpers (k2/k4) =================
__device__ void jacobi16d(double* W, double* V, double* cs) {
    const int t = threadIdx.x;
    for (int i = t; i < 256; i += TB) V[i] = ((i >> 4) == (i & 15)) ? 1.0 : 0.0;
    __syncthreads();
    const int pr = t >> 4, el = t & 15;
    for (int sweep = 0; sweep < SWEEPS_D; ++sweep) {
        for (int r = 0; r < 15; ++r) {
            int p, q;
            if (pr == 0) { p = 15; q = r; }
            else { p = (r + pr) % 15; q = (r + 15 - pr) % 15; }
            if (p < q) { int tmp = p; p = q; q = tmp; }
            if (el == 0) {
                double app = W[p * 16 + p], aqq = W[q * 16 + q], apq = W[p * 16 + q];
                double c = 1.0, s = 0.0;
                if (fabs(apq) > 1e-300) {
                    double tau = (aqq - app) / (2.0 * apq);
                    double tt = copysign(1.0, tau) / (fabs(tau) + sqrt(1.0 + tau * tau));
                    c = rsqrt(1.0 + tt * tt);
                    s = tt * c;
                }
                cs[pr] = c; cs[8 + pr] = s;
            }
            __syncthreads();
            double c = cs[pr], s = cs[8 + pr];
            double wp = W[p * 16 + el], wq = W[q * 16 + el];
            W[p * 16 + el] = c * wp - s * wq;
            W[q * 16 + el] = s * wp + c * wq;
            __syncthreads();
            double xp = W[el * 16 + p], xq = W[el * 16 + q];
            W[el * 16 + p] = c * xp - s * xq;
            W[el * 16 + q] = s * xp + c * xq;
            double vp = V[el * 16 + p], vq = V[el * 16 + q];
            V[el * 16 + p] = c * vp - s * vq;
            V[el * 16 + q] = s * vp + c * vq;
            __syncthreads();
        }
    }
}

__device__ void invert16d(const double* Min, double* aug, double* Mout, double* fs, int* piv) {
    const int t = threadIdx.x;
    for (int i = t; i < 512; i += TB) {
        int r = i >> 5, cc = i & 31;
        aug[i] = (cc < 16) ? Min[r * 16 + cc] : ((cc - 16 == r) ? 1.0 : 0.0);
    }
    __syncthreads();
    for (int k = 0; k < 16; ++k) {
        if (t == 0) {
            int best = k; double bv = fabs(aug[k * 32 + k]);
            for (int i = k + 1; i < 16; ++i) {
                double v = fabs(aug[i * 32 + k]);
                if (v > bv) { bv = v; best = i; }
            }
            *piv = best;
        }
        __syncthreads();
        int pb = *piv;
        if (pb != k && t < 32) {
            double tmp = aug[k * 32 + t];
            aug[k * 32 + t] = aug[pb * 32 + t];
            aug[pb * 32 + t] = tmp;
        }
        __syncthreads();
        if (t == 0) fs[16] = 1.0 / aug[k * 32 + k];
        __syncthreads();
        if (t < 32) aug[k * 32 + t] *= fs[16];
        __syncthreads();
        if (t < 16) fs[t] = aug[t * 32 + k];
        __syncthreads();
        for (int i = t; i < 512; i += TB) {
            int r = i >> 5, cc = i & 31;
            if (r != k) aug[i] -= fs[r] * aug[k * 32 + cc];
        }
        __syncthreads();
    }
    for (int i = t; i < 256; i += TB) Mout[i] = aug[(i >> 4) * 32 + 16 + (i & 15)];
    __syncthreads();
}

__device__ void matmul16d(const double* A, const double* Bm, double* Cc, int m) {
    const int t = threadIdx.x;
    for (int i = t; i < m * 16; i += TB) {
        int r = i >> 4, cc = i & 15;
        double acc = 0.0;
        #pragma unroll
        for (int x = 0; x < 16; ++x) acc += A[r * 16 + x] * Bm[x * 16 + cc];
        Cc[i] = acc;
    }
    __syncthreads();
}

__device__ void gram16d(const double* A, double* W, int m) {
    const int t = threadIdx.x;
    for (int i = t; i < 256; i += TB) {
        int r = i >> 4, cc = i & 15;
        double acc = 0.0;
        for (int x = 0; x < m; ++x) acc += A[x * 16 + r] * A[x * 16 + cc];
        W[i] = acc;
    }
    __syncthreads();
}

__device__ void vdvtd(const double* V, const double* g, double* P) {
    const int t = threadIdx.x;
    for (int i = t; i < 256; i += TB) {
        int r = i >> 4, cc = i & 15;
        double acc = 0.0;
        #pragma unroll
        for (int x = 0; x < 16; ++x) acc += V[r * 16 + x] * g[x] * V[cc * 16 + x];
        P[i] = acc;
    }
    __syncthreads();
}

// ================= kernels =================

// K1 (warp-per-instance): x_log = log_map(X[0,c], X[b,c]) -> gXlog[bc]
__global__ void __launch_bounds__(TB) k1_logmap(const float* __restrict__ X) {
    __shared__ alignas(16) double UTd[WPB][512];   // U (4KB) -> post-eig fp32 scratch
    __shared__ alignas(16) float Zb[WPB][1024];
    __shared__ float Mm[WPB][272];
    __shared__ float Ww[WPB][288];
    __shared__ float Vv[WPB][288];
    const int w = threadIdx.x >> 5, lane = threadIdx.x & 31;
    const int bc = blockIdx.x * WPB + w;
    const int c = bc & (Csz - 1);
    float* U = (float*)UTd[w];
    float* Z = Zb[w];
    float* M = Mm[w];
    float* W = Ww[w];
    float* V = Vv[w];
    const float4* Xp4 = (const float4*)(X + (size_t)bc * 1024);
    const float4* Up4 = (const float4*)(X + (size_t)c * 1024);
    float4* U4 = (float4*)U;
    float4* Z4 = (float4*)Z;
    for (int i = lane; i < 256; i += 32) { U4[i] = Up4[i]; Z4[i] = Xp4[i]; }
    __syncwarp();
    // M = U^T X
    for (int i = lane; i < 256; i += 32) {
        int r = i >> 4, cc = i & 15;
        float acc = 0.f;
        for (int x = 0; x < 64; ++x) acc += U[x * 16 + r] * Z[x * 16 + cc];
        M[r * S17 + cc] = acc;
    }
    __syncwarp();
    // Z = Z - U M
    for (int i = lane; i < 1024; i += 32) {
        int r = i >> 4, cc = i & 15;
        float acc = Z[i];
        #pragma unroll
        for (int x = 0; x < 16; ++x) acc -= U[r * 16 + x] * M[x * S17 + cc];
        Z[i] = acc;
    }
    __syncwarp();
    // W = M M^T (bounded)
    for (int i = lane; i < 256; i += 32) {
        int r = i >> 4, cc = i & 15;
        float acc = 0.f;
        #pragma unroll
        for (int x = 0; x < 16; ++x) acc += M[r * S17 + x] * M[cc * S17 + x];
        W[r * S17 + cc] = acc;
    }
    for (int i = lane; i < 288; i += 32) V[i] = 0.f;
    __syncwarp();
    if (lane < 16) V[lane * S17 + lane] = 1.f;
    jacobi_warp(W, V, lane, SWEEPS_W, true);
    // ---- post-eig: compensated fp32 pipeline (U dead) ----
    float* T1f  = (float*)UTd[w];   // 256
    float* Gm   = T1f + 256;        // 256 (coef, in place)
    float* lamA = T1f + 512;        // 16
    float* invA = T1f + 528;        // 16
    float* sdA  = T1f + 544;        // 16
    // T1 = M^T V with Kahan + TwoProd (absolute error ~2^-48)
    for (int i = lane; i < 256; i += 32) {
        int r = i >> 4, cc = i & 15;
        float s = 0.f, comp = 0.f;
        #pragma unroll
        for (int x = 0; x < 16; ++x) {
            float a = M[x * S17 + r], b = V[x * S17 + cc];
            float p = __fmul_rn(a, b);
            float e = __fmaf_rn(a, b, -p);
            float y = p - comp;
            float t2 = s + y;
            comp = ((t2 - s) - y) - e;
            s = t2;
        }
        T1f[i] = s - comp;
    }
    __syncwarp();
    // lambda_j = ||t_j||^2, inverse
    if (lane < 16) {
        float acc = 0.f;
        #pragma unroll
        for (int r = 0; r < 16; ++r) { float v = T1f[r * 16 + lane]; acc = __fmaf_rn(v, v, acc); }
        acc = fmaxf(acc, 1e-30f);
        lamA[lane] = acc;
        invA[lane] = 1.f / acc;
    }
    __syncwarp();
    // coef[i][j] = (lam_i > lam_j) ? (t_i . t_j)/lam_i : 0
    for (int i = lane; i < 256; i += 32) {
        int r = i >> 4, cc = i & 15;
        float acc = 0.f;
        #pragma unroll
        for (int x = 0; x < 16; ++x)
            acc += T1f[x * 16 + r] * T1f[x * 16 + cc];
        Gm[i] = (lamA[r] > lamA[cc]) ? acc * invA[r] : 0.f;
    }
    __syncwarp();
    // first-order cleanup: t_j -= sum_i coef[i][j] t_i (staged to avoid races)
    {
        float corrReg[8];
        #pragma unroll
        for (int ii = 0; ii < 8; ++ii) {
            int i = lane + 32 * ii, r = i >> 4, cc = i & 15;
            float corr = 0.f;
            #pragma unroll
            for (int x = 0; x < 16; ++x)
                corr += Gm[x * 16 + cc] * T1f[r * 16 + x];
            corrReg[ii] = corr;
        }
        __syncwarp();
        #pragma unroll
        for (int ii = 0; ii < 8; ++ii) T1f[lane + 32 * ii] -= corrReg[ii];
    }
    __syncwarp();
    // recompute lambda on cleaned columns
    if (lane < 16) {
        float acc = 0.f;
        #pragma unroll
        for (int r = 0; r < 16; ++r) { float v = T1f[r * 16 + lane]; acc = __fmaf_rn(v, v, acc); }
        lamA[lane] = fmaxf(acc, 1e-30f);
    }
    __syncwarp();
    if (lane < 16) {
        double lam = (double)lamA[lane];
        double om = fmax(1.0 - lam, 0.0);
        double alpha = (om < 1e-28) ? 1.0 : atan(sqrt(om / lam)) / sqrt(om);
        sdA[lane] = (float)(alpha / sqrt(lam));
    }
    __syncwarp();
    // Ts (bounded) into M
    for (int i = lane; i < 256; i += 32)
        M[(i >> 4) * S17 + (i & 15)] = T1f[i] * sdA[i & 15];
    __syncwarp();
    // G = Ts V^T into W
    for (int i = lane; i < 256; i += 32) {
        int r = i >> 4, cc = i & 15;
        float acc = 0.f;
        #pragma unroll
        for (int x = 0; x < 16; ++x) acc += M[r * S17 + x] * V[cc * S17 + x];
        W[r * S17 + cc] = acc;
    }
    __syncwarp();
    // x_log = Z G -> gXlog
    float4* dst4 = (float4*)(gXlog + (size_t)bc * 1024);
    for (int i4 = lane; i4 < 256; i4 += 32) {
        int r = i4 >> 2, cb = (i4 & 3) * 4;
        float a0 = 0.f, a1 = 0.f, a2 = 0.f, a3 = 0.f;
        #pragma unroll
        for (int x = 0; x < 16; ++x) {
            float z = Z[r * 16 + x];
            a0 += z * W[x * S17 + cb];
            a1 += z * W[x * S17 + cb + 1];
            a2 += z * W[x * S17 + cb + 2];
            a3 += z * W[x * S17 + cb + 3];
        }
        dst4[i4] = make_float4(a0, a1, a2, a3);
    }
}

// K2 (per channel, fp64): reduce x_log, exp_map mean, Bm, GinvC
__global__ void k2_mean(const float* __restrict__ X, float* __restrict__ meanOut) {
    __shared__ double Dm[1024], U0[1024], meanS[1024], Cm[768];
    __shared__ double W[256], V[256], M1[256], M2[256], aug[512];
    __shared__ double g[32], cs[16], fs[18];
    __shared__ int piv;
    const int c = blockIdx.x;
    const int t = threadIdx.x;
    const float4* gX4 = (const float4*)gXlog;
    for (int i4 = t; i4 < 256; i4 += TB) {
        double a0 = 0.0, a1 = 0.0, a2 = 0.0, a3 = 0.0;
        #pragma unroll 4
        for (int b = 0; b < Bsz; ++b) {
            float4 v = gX4[((size_t)b * Csz + c) * 256 + i4];
            a0 += v.x; a1 += v.y; a2 += v.z; a3 += v.w;
        }
        const double inv = 1.0 / (double)Bsz;
        int i = i4 * 4;
        Dm[i] = a0 * inv; Dm[i + 1] = a1 * inv; Dm[i + 2] = a2 * inv; Dm[i + 3] = a3 * inv;
    }
    for (int i = t; i < 1024; i += TB)
        U0[i] = (double)X[(size_t)c * 1024 + i];
    __syncthreads();
    gram16d(Dm, W, 64);
    jacobi16d(W, V, cs);
    if (t < 16) {
        double S = sqrt(fmax(W[t * 17], 0.0));
        g[t] = cos(S);
        g[16 + t] = (S > 1e-100) ? sin(S) / S : 1.0;
    }
    __syncthreads();
    vdvtd(V, g, M1);
    vdvtd(V, g + 16, M2);
    for (int i = t; i < 1024; i += TB) {
        int r = i >> 4, cc = i & 15;
        double acc = 0.0;
        #pragma unroll
        for (int x = 0; x < 16; ++x)
            acc += U0[r * 16 + x] * M1[x * 16 + cc] + Dm[r * 16 + x] * M2[x * 16 + cc];
        meanS[i] = acc;
        meanOut[c * 1024 + i] = (float)acc;
    }
    __syncthreads();
    invert16d(meanS, aug, M1, fs, &piv);
    matmul16d(meanS + 256, M1, Cm, 48);
    gram16d(Cm, W, 48);
    jacobi16d(W, V, cs);
    if (t < 16) {
        double S = sqrt(fmax(W[t * 17], 0.0));
        g[t] = (S > 1e-100) ? atan(S) / S : 1.0;
    }
    __syncthreads();
    vdvtd(V, g, M2);
    matmul16d(Cm, M2, Dm, 48);
    for (int i = t; i < 768; i += TB) gBmF[c * 768 + i] = (float)Dm[i];
    __syncthreads();
    gram16d(Dm, W, 48);
    for (int i = t; i < 256; i += TB) {
        int r = i >> 4, cc = i & 15;
        W[i] = 0.25 * W[i] + ((r == cc) ? 1.0 : 0.0);
    }
    __syncthreads();
    invert16d(W, aug, M1, fs, &piv);
    for (int i = t; i < 256; i += TB) gGinvCF[c * 256 + i] = (float)M1[i];
}

// K3 (warp-per-instance): theta^2 sum -> gTheta[bc]
__global__ void __launch_bounds__(TB) k3_theta(const float* __restrict__ X,
                                               const float* __restrict__ meanIn) {
    __shared__ alignas(16) float Mn[WPB][1024];
    __shared__ alignas(16) float Xb[WPB][1024];
    __shared__ float Mm[WPB][272], Ww[WPB][288];
    const int w = threadIdx.x >> 5, lane = threadIdx.x & 31;
    const int bc = blockIdx.x * WPB + w;
    const int c = bc & (Csz - 1);
    float* A = Mn[w];
    float* Xl = Xb[w];
    float* M = Mm[w];
    float* W = Ww[w];
    const float4* Xp4 = (const float4*)(X + (size_t)bc * 1024);
    const float4* Mp4 = (const float4*)(meanIn + (size_t)c * 1024);
    float4* A4 = (float4*)A;
    float4* Xl4 = (float4*)Xl;
    for (int i = lane; i < 256; i += 32) { A4[i] = Mp4[i]; Xl4[i] = Xp4[i]; }
    __syncwarp();
    for (int i = lane; i < 256; i += 32) {
        int r = i >> 4, cc = i & 15;
        float acc = 0.f;
        for (int x = 0; x < 64; ++x) acc += A[x * 16 + r] * Xl[x * 16 + cc];
        M[r * S17 + cc] = acc;
    }
    __syncwarp();
    for (int i = lane; i < 256; i += 32) {
        int r = i >> 4, cc = i & 15;
        float acc = 0.f;
        #pragma unroll
        for (int x = 0; x < 16; ++x) acc += M[x * S17 + r] * M[x * S17 + cc];
        W[r * S17 + cc] = acc;
    }
    jacobi_warp(W, (float*)0, lane, SWEEPS_NV, false);
    if (lane == 0) {
        float sum = 0.f;
        for (int j2 = 0; j2 < 16; ++j2) {
            float s = sqrtf(fmaxf(W[j2 * 18], 0.f));
            s = fminf(s, 1.f);
            float th = acosf(s);
            sum += th * th;
        }
        gTheta[bc] = sum;
    }
}

// K4 (grid=Csz): per-channel factor via tree reduction; block 0 also bias Ginv
__global__ void k4_factor(const float* __restrict__ bias, const float* __restrict__ shiftp) {
    __shared__ float red[TB];
    __shared__ double Bb[768], W[256], M1[256], aug[512], fs[18];
    __shared__ int piv;
    const int t = threadIdx.x;
    const int c = blockIdx.x;
    red[t] = gTheta[t * Csz + c] + gTheta[(t + TB) * Csz + c];
    __syncthreads();
    for (int s = TB / 2; s > 0; s >>= 1) {
        if (t < s) red[t] += red[t + s];
        __syncthreads();
    }
    if (t == 0) {
        double var = (double)red[0] * (1.0 / (double)Bsz);
        gFactorF[c] = (float)((double)shiftp[0] / sqrt(var + 1e-5));
    }
    if (c == 0) {
        for (int i = t; i < 768; i += TB) Bb[i] = (double)bias[i];
        __syncthreads();
        gram16d(Bb, W, 48);
        for (int i = t; i < 256; i += TB) {
            int r = i >> 4, cc = i & 15;
            W[i] = 0.25 * W[i] + ((r == cc) ? 1.0 : 0.0);
        }
        __syncthreads();
        invert16d(W, aug, M1, fs, &piv);
        for (int i = t; i < 256; i += TB) gGinvBF[i] = (float)M1[i];
    }
}

// K5 (warp-per-instance): center -> gyro scale -> bias
__global__ void __launch_bounds__(TB) k5_final(const float* __restrict__ X,
                                               const float* __restrict__ bias,
                                               float* __restrict__ out) {
    __shared__ alignas(16) float Xs[WPB][1024];
    __shared__ alignas(16) float Bmw[WPB][768];
    __shared__ alignas(16) double bufd[WPB][256];   // 512 floats scratch
    __shared__ float Vv[WPB][288];
    __shared__ alignas(16) float Tt[WPB][256];
    __shared__ float lamK[WPB][16], invK[WPB][16], sdK[WPB][16], gkK[WPB][16];
    const int w = threadIdx.x >> 5, lane = threadIdx.x & 31;
    const int bc = blockIdx.x * WPB + w;
    const int c = bc & (Csz - 1);
    float* Xw = Xs[w];
    float* Bw = Bmw[w];
    float* buf_f = (float*)bufd[w];
    float* V = Vv[w];
    float* T = Tt[w];
    {
        const float4* Xp4 = (const float4*)(X + (size_t)bc * 1024);
        const float4* Bm4 = (const float4*)(gBmF + (size_t)c * 768);
        const float4* Gi4 = (const float4*)(gGinvCF + (size_t)c * 256);
        float4* Xw4 = (float4*)Xw;
        float4* Bw4 = (float4*)Bw;
        float4* bf4 = (float4*)buf_f;
        for (int i = lane; i < 256; i += 32) Xw4[i] = Xp4[i];
        for (int i = lane; i < 192; i += 32) Bw4[i] = Bm4[i];
        for (int i = lane; i < 64; i += 32) bf4[i] = Gi4[i];
    }
    __syncwarp();
    // --- Step A: centering Cayley ---
    for (int i = lane; i < 256; i += 32) {
        int r = i >> 4, cc = i & 15;
        float acc = Xw[i];
        for (int k = 0; k < 48; ++k)
            acc += 0.5f * Bw[k * 16 + r] * Xw[256 + k * 16 + cc];
        T[i] = acc;
    }
    __syncwarp();
    {
        float yreg[8];
        #pragma unroll
        for (int ii = 0; ii < 8; ++ii) {
            int i = lane + 32 * ii, r = i >> 4, cc = i & 15;
            float acc = 0.f;
            #pragma unroll
            for (int x = 0; x < 16; ++x) acc += buf_f[r * 16 + x] * T[x * 16 + cc];
            yreg[ii] = acc;
        }
        __syncwarp();
        #pragma unroll
        for (int ii = 0; ii < 8; ++ii) T[lane + 32 * ii] = yreg[ii];
    }
    __syncwarp();
    for (int i = lane; i < 1024; i += 32) {
        if (i < 256) Xw[i] = 2.f * T[i] - Xw[i];
        else {
            int r = (i - 256) >> 4, cc = i & 15;
            float acc = Xw[i];
            #pragma unroll
            for (int x = 0; x < 16; ++x) acc -= Bw[r * 16 + x] * T[x * 16 + cc];
            Xw[i] = acc;
        }
    }
    __syncwarp();
    // --- Step B: gyro scaling via K = Xu Xu^T ---
    float* W = buf_f;
    for (int i = lane; i < 256; i += 32) {
        int r = i >> 4, cc = i & 15;
        float acc = 0.f;
        #pragma unroll
        for (int x = 0; x < 16; ++x) acc += Xw[r * 16 + x] * Xw[cc * 16 + x];
        W[r * S17 + cc] = acc;
    }
    for (int i = lane; i < 288; i += 32) V[i] = 0.f;
    __syncwarp();
    if (lane < 16) V[lane * S17 + lane] = 1.f;
    jacobi_warp(W, V, lane, SWEEPS_W, true);
    // ---- post-eig: compensated fp32 pipeline (W dead) ----
    float* T1f = buf_f;          // 256
    float* Gm  = buf_f + 256;    // 256
    for (int i = lane; i < 256; i += 32) {
        int r = i >> 4, cc = i & 15;
        float s = 0.f, comp = 0.f;
        #pragma unroll
        for (int x = 0; x < 16; ++x) {
            float a = Xw[x * 16 + r], b = V[x * S17 + cc];
            float p = __fmul_rn(a, b);
            float e = __fmaf_rn(a, b, -p);
            float y = p - comp;
            float t2 = s + y;
            comp = ((t2 - s) - y) - e;
            s = t2;
        }
        T1f[i] = s - comp;
    }
    __syncwarp();
    if (lane < 16) {
        float acc = 0.f;
        #pragma unroll
        for (int r = 0; r < 16; ++r) { float v = T1f[r * 16 + lane]; acc = __fmaf_rn(v, v, acc); }
        acc = fmaxf(acc, 1e-30f);
        lamK[w][lane] = acc;
        invK[w][lane] = 1.f / acc;
    }
    __syncwarp();
    for (int i = lane; i < 256; i += 32) {
        int r = i >> 4, cc = i & 15;
        float acc = 0.f;
        #pragma unroll
        for (int x = 0; x < 16; ++x)
            acc += T1f[x * 16 + r] * T1f[x * 16 + cc];
        Gm[i] = (lamK[w][r] > lamK[w][cc]) ? acc * invK[w][r] : 0.f;
    }
    __syncwarp();
    {
        float corrReg[8];
        #pragma unroll
        for (int ii = 0; ii < 8; ++ii) {
            int i = lane + 32 * ii, r = i >> 4, cc = i & 15;
            float corr = 0.f;
            #pragma unroll
            for (int x = 0; x < 16; ++x)
                corr += Gm[x * 16 + cc] * T1f[r * 16 + x];
            corrReg[ii] = corr;
        }
        __syncwarp();
        #pragma unroll
        for (int ii = 0; ii < 8; ++ii) T1f[lane + 32 * ii] -= corrReg[ii];
    }
    __syncwarp();
    if (lane < 16) {
        float acc = 0.f;
        #pragma unroll
        for (int r = 0; r < 16; ++r) { float v = T1f[r * 16 + lane]; acc = __fmaf_rn(v, v, acc); }
        lamK[w][lane] = fmaxf(acc, 1e-30f);
    }
    __syncwarp();
    float fct = gFactorF[c];
    if (lane < 16) {
        double lam = (double)lamK[w][lane];
        double om = fmax(1.0 - lam, 0.0);
        double beta, cth;
        if (om < 1e-28) { beta = (double)fct; cth = 1.0; }
        else {
            double th = (double)fct * atan(sqrt(om / lam));
            beta = sin(th) / sqrt(om);
            cth = cos(th);
        }
        sdK[w][lane] = (float)(beta / sqrt(lam));
        gkK[w][lane] = (float)cth;
    }
    __syncwarp();
    // Ts into Gm's slot (coef dead)
    float* Tsf = buf_f + 256;
    for (int i = lane; i < 256; i += 32) Tsf[i] = T1f[i] * sdK[w][i & 15];
    __syncwarp();
    // M2 = Ts V^T into buf_f[0..255] (T1f dead)
    float* M2f = buf_f;
    for (int i = lane; i < 256; i += 32) {
        int r = i >> 4, cc = i & 15;
        float acc = 0.f;
        #pragma unroll
        for (int x = 0; x < 16; ++x) acc += Tsf[r * 16 + x] * V[cc * S17 + x];
        M2f[i] = acc;
    }
    __syncwarp();
    // top = V cos V^T into T
    for (int i = lane; i < 256; i += 32) {
        int r = i >> 4, cc = i & 15;
        float acc = 0.f;
        #pragma unroll
        for (int x = 0; x < 16; ++x) acc += V[r * S17 + x] * gkK[w][x] * V[cc * S17 + x];
        T[i] = acc;
    }
    // bot = Xl M2 into Bw (Bm dead)
    for (int i = lane; i < 768; i += 32) {
        int r = i >> 4, cc = i & 15;
        float acc = 0.f;
        #pragma unroll
        for (int x = 0; x < 16; ++x) acc += Xw[256 + r * 16 + x] * M2f[x * 16 + cc];
        Bw[i] = acc;
    }
    __syncwarp();
    {
        float4* Xw4 = (float4*)Xw;
        float4* T4 = (float4*)T;
        float4* Bw4 = (float4*)Bw;
        for (int i = lane; i < 64; i += 32) Xw4[i] = T4[i];
        for (int i = lane; i < 192; i += 32) Xw4[64 + i] = Bw4[i];
    }
    __syncwarp();
    // --- Step C: bias Cayley ---
    {
        const float4* b4 = (const float4*)bias;
        const float4* g4 = (const float4*)gGinvBF;
        float4* Bw4 = (float4*)Bw;
        float4* bf4 = (float4*)buf_f;
        for (int i = lane; i < 192; i += 32) Bw4[i] = b4[i];
        for (int i = lane; i < 64; i += 32) bf4[i] = g4[i];
    }
    __syncwarp();
    for (int i = lane; i < 256; i += 32) {
        int r = i >> 4, cc = i & 15;
        float acc = Xw[i];
        for (int k = 0; k < 48; ++k)
            acc -= 0.5f * Bw[k * 16 + r] * Xw[256 + k * 16 + cc];
        T[i] = acc;
    }
    __syncwarp();
    {
        float yreg[8];
        #pragma unroll
        for (int ii = 0; ii < 8; ++ii) {
            int i = lane + 32 * ii, r = i >> 4, cc = i & 15;
            float acc = 0.f;
            #pragma unroll
            for (int x = 0; x < 16; ++x) acc += buf_f[r * 16 + x] * T[x * 16 + cc];
            yreg[ii] = acc;
        }
        __syncwarp();
        #pragma unroll
        for (int ii = 0; ii < 8; ++ii) T[lane + 32 * ii] = yreg[ii];
    }
    __syncwarp();
    float4* dst4 = (float4*)(out + (size_t)bc * 1024);
    for (int i4 = lane; i4 < 64; i4 += 32) {
        float4 t4 = ((float4*)T)[i4];
        float4 x4 = ((float4*)Xw)[i4];
        dst4[i4] = make_float4(2.f * t4.x - x4.x, 2.f * t4.y - x4.y,
                               2.f * t4.z - x4.z, 2.f * t4.w - x4.w);
    }
    for (int i4 = lane; i4 < 192; i4 += 32) {
        int r = i4 >> 2, cb = (i4 & 3) * 4;
        float a0 = Xw[256 + r * 16 + cb];
        float a1 = Xw[256 + r * 16 + cb + 1];
        float a2 = Xw[256 + r * 16 + cb + 2];
        float a3 = Xw[256 + r * 16 + cb + 3];
        #pragma unroll
        for (int x = 0; x < 16; ++x) {
            float bv = Bw[r * 16 + x];
            a0 += bv * T[x * 16 + cb];
            a1 += bv * T[x * 16 + cb + 1];
            a2 += bv * T[x * 16 + cb + 2];
            a3 += bv * T[x * 16 + cb + 3];
        }
        dst4[64 + i4] = make_float4(a0, a1, a2, a3);
    }
}

// ---------------- launch ----------------
extern "C" void kernel_launch(void* const* d_in, const int* in_sizes, int n_in,
                              void* d_out, int out_size) {
    const float* X = (const float*)d_in[0];
    const float* bias = (const float*)d_in[1];
    const float* shift = (const float*)d_in[2];
    float* out = (float*)d_out;
    float* meanOut = out + (size_t)Bsz * Csz * Nsz * Psz;

    const int nInst = Bsz * Csz;
    k1_logmap<<<nInst / WPB, TB>>>(X);
    k2_mean<<<Csz, TB>>>(X, meanOut);
    k3_theta<<<nInst / WPB, TB>>>(X, meanOut);
    k4_factor<<<Csz, TB>>>(bias, shift);
    k5_final<<<nInst / WPB, TB>>>(X, bias, out);
}